// round 3
// baseline (speedup 1.0000x reference)
#include <cuda_runtime.h>
#include <cstdint>

#define BATCHN 256
#define SEQLEN 512
#define NEMB   300
#define NHID   256

typedef unsigned long long ull;

// ---------- packed f32x2 helpers (sm_103a FFMA2 path) ----------
__device__ __forceinline__ void fma2(ull &d, ull a, ull b) {
    asm("fma.rn.f32x2 %0, %1, %2, %0;" : "+l"(d) : "l"(a), "l"(b));
}
__device__ __forceinline__ ull pack2(float x, float y) {
    ull r; asm("mov.b64 %0, {%1, %2};" : "=l"(r) : "f"(x), "f"(y)); return r;
}
__device__ __forceinline__ float2 unpack2(ull v) {
    float2 r; asm("mov.b64 {%0, %1}, %2;" : "=f"(r.x), "=f"(r.y) : "l"(v)); return r;
}
__device__ __forceinline__ float sigmoidf(float z) {
    return 1.0f / (1.0f + __expf(-z));
}

// Scratch: X[t][b][h] = (emb[words[b][t]] @ Wi), time-major. 128 MB device global.
__device__ float g_X[SEQLEN * BATCHN * NHID];

// =====================================================================
// Phase 1: X = gather(emb) @ Wi.  Rows r = t*256 + b (131072), cols 256.
// 128x64 tiles, K in 15 chunks of 20.
// Micro-tile 4x8: A pre-DUPLICATED in smem as (a,a) 64-bit words (read via
// broadcast LDS.128, ~free on crossbar), B read as natural f32x2 pairs.
// -> inner loop has ZERO pack movs: 16 fma2 + 4 LDS.128 per k per thread.
// =====================================================================
__global__ __launch_bounds__(256, 2) void x_gemm_kernel(
    const int* __restrict__ words,
    const float* __restrict__ emb,
    const float* __restrict__ Wi)
{
    __shared__ int wsm[128];
    __shared__ __align__(16) ull   As2[20][128];  // duplicated A: (a,a)
    __shared__ __align__(16) float Bs[20][64];

    const int tid   = threadIdx.x;
    const int rbase = blockIdx.x * 128;
    const int cbase = blockIdx.y * 64;

    if (tid < 128) {
        int r = rbase + tid;
        wsm[tid] = words[(r & 255) * SEQLEN + (r >> 8)];
    }
    __syncthreads();

    const int tm = tid >> 3;    // 0..31 -> rows tm*4 .. tm*4+3
    const int tn = tid & 7;     // 0..7  -> cols tn*8 .. tn*8+7

    ull acc[4][4];
    #pragma unroll
    for (int m = 0; m < 4; m++)
        #pragma unroll
        for (int p = 0; p < 4; p++) acc[m][p] = 0ULL;

    // prefetch regs: A chunk = 128 rows x 20 k = 1280 float2-elems (5/thread)
    //                B chunk = 20 k x 64 cols = 1280 floats      (5/thread)
    float2 pa[5];
    float  pb[5];

    #pragma unroll
    for (int l = 0; l < 5; l++) {
        int e = tid + l * 256;
        int m = e / 10, kp = e % 10;
        pa[l] = *(const float2*)&emb[(long long)wsm[m] * NEMB + 2 * kp];
        int k = e >> 6, n = e & 63;
        pb[l] = Wi[k * NHID + cbase + n];
    }

    for (int c = 0; c < 15; c++) {
        // commit prefetched chunk to smem (A duplicated)
        #pragma unroll
        for (int l = 0; l < 5; l++) {
            int e = tid + l * 256;
            int m = e / 10, kp = e % 10;
            As2[2 * kp][m]     = pack2(pa[l].x, pa[l].x);
            As2[2 * kp + 1][m] = pack2(pa[l].y, pa[l].y);
            int k = e >> 6, n = e & 63;
            Bs[k][n] = pb[l];
        }
        __syncthreads();

        if (c + 1 < 15) {
            int k0 = (c + 1) * 20;
            #pragma unroll
            for (int l = 0; l < 5; l++) {
                int e = tid + l * 256;
                int m = e / 10, kp = e % 10;
                pa[l] = *(const float2*)&emb[(long long)wsm[m] * NEMB + k0 + 2 * kp];
                int k = e >> 6, n = e & 63;
                pb[l] = Wi[(k0 + k) * NHID + cbase + n];
            }
        }

        #pragma unroll
        for (int k = 0; k < 20; k++) {
            // A: 4 duplicated rows, broadcast within warp (2 x LDS.128)
            ulonglong2 a01 = *(const ulonglong2*)&As2[k][tm * 4];
            ulonglong2 a23 = *(const ulonglong2*)&As2[k][tm * 4 + 2];
            // B: 8 cols as 4 natural f32x2 pairs (2 x LDS.128)
            ulonglong2 b01 = *(const ulonglong2*)&Bs[k][tn * 8];
            ulonglong2 b23 = *(const ulonglong2*)&Bs[k][tn * 8 + 4];
            fma2(acc[0][0], a01.x, b01.x); fma2(acc[0][1], a01.x, b01.y);
            fma2(acc[0][2], a01.x, b23.x); fma2(acc[0][3], a01.x, b23.y);
            fma2(acc[1][0], a01.y, b01.x); fma2(acc[1][1], a01.y, b01.y);
            fma2(acc[1][2], a01.y, b23.x); fma2(acc[1][3], a01.y, b23.y);
            fma2(acc[2][0], a23.x, b01.x); fma2(acc[2][1], a23.x, b01.y);
            fma2(acc[2][2], a23.x, b23.x); fma2(acc[2][3], a23.x, b23.y);
            fma2(acc[3][0], a23.y, b01.x); fma2(acc[3][1], a23.y, b01.y);
            fma2(acc[3][2], a23.y, b23.x); fma2(acc[3][3], a23.y, b23.y);
        }
        __syncthreads();
    }

    #pragma unroll
    for (int m = 0; m < 4; m++) {
        int row = rbase + tm * 4 + m;
        float* dst = &g_X[(long long)row * NHID + cbase + tn * 8];
        *(ulonglong2*)(dst)     = make_ulonglong2(acc[m][0], acc[m][1]);
        *(ulonglong2*)(dst + 4) = make_ulonglong2(acc[m][2], acc[m][3]);
    }
}

// =====================================================================
// Phase 2: recurrence. 128 CTAs x 256 threads, 2 batch rows/CTA,
// thread j owns column j for both rows.
// Wh rows 0..95 in smem (96 KB), rows 96..255 in registers (160 regs).
// h double-buffered in smem -> ONE barrier per step.
// =====================================================================
#define SQ 24   // smem k4-groups  (rows 0..95)
#define RQ 40   // reg  k4-groups  (rows 96..255)
#define P2_SMEM (SQ * 256 * 16 + 2 * 512 * 4)

__global__ void __launch_bounds__(256, 1) rnn_kernel(
    const float* __restrict__ Wh,
    const float* __restrict__ fcw,
    const float* __restrict__ fcb,
    float* __restrict__ out)
{
    extern __shared__ __align__(16) char smem[];
    ulonglong2* WhS = (ulonglong2*)smem;                    // [SQ*256]
    float*      hb  = (float*)(smem + SQ * 256 * 16);       // [2][2][256]

    const int j  = threadIdx.x;            // column 0..255
    const int r0 = blockIdx.x * 2;
    const int r1 = r0 + 1;

    // Wh rows 0..95 -> smem, packed float4-over-k: WhS[q][c] = Wh[4q..4q+3][c]
    for (int i = j; i < SQ * 256; i += 256) {
        int q = i >> 8, c = i & 255, kr = 4 * q;
        float4 v = make_float4(Wh[kr * NHID + c],       Wh[(kr + 1) * NHID + c],
                               Wh[(kr + 2) * NHID + c], Wh[(kr + 3) * NHID + c]);
        ((float4*)smem)[i] = v;
    }
    // Wh rows 96..255, col j -> registers
    ulonglong2 whr[RQ];
    #pragma unroll
    for (int q = 0; q < RQ; q++) {
        int kr = 96 + 4 * q;
        whr[q].x = pack2(Wh[kr * NHID + j],       Wh[(kr + 1) * NHID + j]);
        whr[q].y = pack2(Wh[(kr + 2) * NHID + j], Wh[(kr + 3) * NHID + j]);
    }
    hb[j] = 0.f; hb[256 + j] = 0.f;   // h0 = 0 in buffer 0
    __syncthreads();

    float x0 = g_X[r0 * NHID + j];
    float x1 = g_X[r1 * NHID + j];

    int buf = 0;
    for (int t = 0; t < SEQLEN; t++) {
        const ulonglong2* H0 = (const ulonglong2*)(hb + buf * 512);
        const ulonglong2* H1 = H0 + 64;

        ull a0 = 0, a1 = 0;
        #pragma unroll 8
        for (int q = 0; q < SQ; q++) {
            ulonglong2 w  = WhS[q * 256 + j];
            ulonglong2 h0 = H0[q];
            ulonglong2 h1 = H1[q];
            fma2(a0, h0.x, w.x); fma2(a0, h0.y, w.y);
            fma2(a1, h1.x, w.x); fma2(a1, h1.y, w.y);
        }
        #pragma unroll
        for (int q = 0; q < RQ; q++) {
            ulonglong2 h0 = H0[SQ + q];
            ulonglong2 h1 = H1[SQ + q];
            fma2(a0, h0.x, whr[q].x); fma2(a0, h0.y, whr[q].y);
            fma2(a1, h1.x, whr[q].x); fma2(a1, h1.y, whr[q].y);
        }

        float2 s0 = unpack2(a0), s1 = unpack2(a1);
        float hn0 = sigmoidf(x0 + s0.x + s0.y);
        float hn1 = sigmoidf(x1 + s1.x + s1.y);

        if (t + 1 < SEQLEN) {
            const float* xp = g_X + (t + 1) * (BATCHN * NHID);
            x0 = xp[r0 * NHID + j];
            x1 = xp[r1 * NHID + j];
        }

        int nb = buf ^ 1;
        hb[nb * 512 + j]       = hn0;
        hb[nb * 512 + 256 + j] = hn1;
        __syncthreads();
        buf = nb;
    }

    float hf0 = hb[buf * 512 + j];
    float hf1 = hb[buf * 512 + 256 + j];
    out[256 + r0 * NHID + j] = hf0;
    out[256 + r1 * NHID + j] = hf1;

    // sig = sigmoid(h @ fc_w + fc_b): warp 0 -> row r0, warp 1 -> row r1
    int w = j >> 5, l = j & 31;
    if (w < 2) {
        float s = 0.f;
        #pragma unroll
        for (int q = 0; q < 8; q++)
            s += hb[buf * 512 + w * 256 + l + q * 32] * fcw[l + q * 32];
        #pragma unroll
        for (int o = 16; o; o >>= 1)
            s += __shfl_xor_sync(0xffffffffu, s, o);
        if (l == 0)
            out[r0 + w] = sigmoidf(s + fcb[0]);
    }
}

// =====================================================================
extern "C" void kernel_launch(void* const* d_in, const int* in_sizes, int n_in,
                              void* d_out, int out_size)
{
    const int*   words = (const int*)  d_in[0];
    const float* emb   = (const float*)d_in[1];
    const float* Wi    = (const float*)d_in[2];
    const float* Wh    = (const float*)d_in[3];
    const float* fcw   = (const float*)d_in[4];
    const float* fcb   = (const float*)d_in[5];
    float*       out   = (float*)d_out;

    cudaFuncSetAttribute(rnn_kernel, cudaFuncAttributeMaxDynamicSharedMemorySize, P2_SMEM);

    x_gemm_kernel<<<dim3((SEQLEN * BATCHN) / 128, NHID / 64), 256>>>(words, emb, Wi);
    rnn_kernel<<<BATCHN / 2, 256, P2_SMEM>>>(Wh, fcw, fcb, out);
}

// round 4
// speedup vs baseline: 1.0204x; 1.0204x over previous
#include <cuda_runtime.h>
#include <cstdint>

#define BATCHN 256
#define SEQLEN 512
#define NEMB   300
#define NHID   256

typedef unsigned long long ull;

// ---------- packed f32x2 helpers (sm_103a FFMA2 path) ----------
__device__ __forceinline__ void fma2(ull &d, ull a, ull b) {
    asm("fma.rn.f32x2 %0, %1, %2, %0;" : "+l"(d) : "l"(a), "l"(b));
}
__device__ __forceinline__ ull pack2(float x, float y) {
    ull r; asm("mov.b64 %0, {%1, %2};" : "=l"(r) : "f"(x), "f"(y)); return r;
}
__device__ __forceinline__ float2 unpack2(ull v) {
    float2 r; asm("mov.b64 {%0, %1}, %2;" : "=f"(r.x), "=f"(r.y) : "l"(v)); return r;
}
__device__ __forceinline__ float sigmoidf(float z) {
    return 1.0f / (1.0f + __expf(-z));
}

// Scratch: X[t][b][h] = (emb[words[b][t]] @ Wi), time-major. 128 MB device global.
__device__ float g_X[SEQLEN * BATCHN * NHID];

// =====================================================================
// Phase 1: X = gather(emb) @ Wi.  Rows r = t*256 + b (131072), cols 256.
// 64x64 tiles, K in 15 chunks of 20.
// Micro-tile 4x4. A pre-DUPLICATED in smem as (a,a) ull (broadcast LDS.64),
// B read as natural contiguous f32x2 pairs. Inner loop: ZERO pack movs,
// 8 fma2 + 6 LDS.64 per k. acc = 16 ull = 32 regs (fits occ 2).
// =====================================================================
__global__ __launch_bounds__(256, 2) void x_gemm_kernel(
    const int* __restrict__ words,
    const float* __restrict__ emb,
    const float* __restrict__ Wi)
{
    __shared__ int wsm[64];
    __shared__ __align__(16) ull   Adup[20][64];  // (a,a) duplicated, 10 KB
    __shared__ __align__(16) float Bs[20][64];    // 5 KB

    const int tid   = threadIdx.x;
    const int rbase = blockIdx.x * 64;
    const int cbase = blockIdx.y * 64;

    if (tid < 64) {
        int r = rbase + tid;
        wsm[tid] = words[(r & 255) * SEQLEN + (r >> 8)];
    }
    __syncthreads();

    const int tm4 = (tid >> 4) * 4;   // rows tm4 .. tm4+3  (16 groups)
    const int tn4 = (tid & 15) * 4;   // cols tn4 .. tn4+3  (16 groups)

    ull acc[4][2];
    #pragma unroll
    for (int i = 0; i < 4; i++) { acc[i][0] = 0ULL; acc[i][1] = 0ULL; }

    // A chunk = 64 rows x 20 k = 640 float2 elements; threads 0..127 carry a 3rd.
    float2 pa0, pa1, pa2;
    const bool has3 = (tid < 128);

    // prefetch chunk 0 A
    {
        int e0 = tid,        m0 = e0 / 10, kp0 = e0 % 10;
        int e1 = tid + 256,  m1 = e1 / 10, kp1 = e1 % 10;
        pa0 = *(const float2*)&emb[(long long)wsm[m0] * NEMB + 2 * kp0];
        pa1 = *(const float2*)&emb[(long long)wsm[m1] * NEMB + 2 * kp1];
        if (has3) {
            int e2 = tid + 512, m2 = e2 / 10, kp2 = e2 % 10;
            pa2 = *(const float2*)&emb[(long long)wsm[m2] * NEMB + 2 * kp2];
        }
    }

    for (int c = 0; c < 15; c++) {
        const int k0 = c * 20;

        // commit A (duplicated) to smem
        {
            int e0 = tid,        m0 = e0 / 10, kp0 = e0 % 10;
            int e1 = tid + 256,  m1 = e1 / 10, kp1 = e1 % 10;
            Adup[2 * kp0][m0]     = pack2(pa0.x, pa0.x);
            Adup[2 * kp0 + 1][m0] = pack2(pa0.y, pa0.y);
            Adup[2 * kp1][m1]     = pack2(pa1.x, pa1.x);
            Adup[2 * kp1 + 1][m1] = pack2(pa1.y, pa1.y);
            if (has3) {
                int e2 = tid + 512, m2 = e2 / 10, kp2 = e2 % 10;
                Adup[2 * kp2][m2]     = pack2(pa2.x, pa2.x);
                Adup[2 * kp2 + 1][m2] = pack2(pa2.y, pa2.y);
            }
        }
        // B: 20k x 64n, load straight from L2 (Wi is small & hot), float2 pairs
        #pragma unroll
        for (int i = tid; i < 640; i += 256) {
            int k = i >> 5, n2 = (i & 31) * 2;
            float2 v = *(const float2*)&Wi[(k0 + k) * NHID + cbase + n2];
            *(float2*)&Bs[k][n2] = v;
        }
        __syncthreads();

        // prefetch next A chunk (hides under compute)
        if (c + 1 < 15) {
            int kn = k0 + 20;
            int e0 = tid,        m0 = e0 / 10, kp0 = e0 % 10;
            int e1 = tid + 256,  m1 = e1 / 10, kp1 = e1 % 10;
            pa0 = *(const float2*)&emb[(long long)wsm[m0] * NEMB + kn + 2 * kp0];
            pa1 = *(const float2*)&emb[(long long)wsm[m1] * NEMB + kn + 2 * kp1];
            if (has3) {
                int e2 = tid + 512, m2 = e2 / 10, kp2 = e2 % 10;
                pa2 = *(const float2*)&emb[(long long)wsm[m2] * NEMB + kn + 2 * kp2];
            }
        }

        #pragma unroll
        for (int k = 0; k < 20; k++) {
            ull a0 = Adup[k][tm4 + 0];
            ull a1 = Adup[k][tm4 + 1];
            ull a2 = Adup[k][tm4 + 2];
            ull a3 = Adup[k][tm4 + 3];
            ull b0 = *(const ull*)&Bs[k][tn4];       // (b[n], b[n+1])
            ull b1 = *(const ull*)&Bs[k][tn4 + 2];   // (b[n+2], b[n+3])
            fma2(acc[0][0], a0, b0); fma2(acc[0][1], a0, b1);
            fma2(acc[1][0], a1, b0); fma2(acc[1][1], a1, b1);
            fma2(acc[2][0], a2, b0); fma2(acc[2][1], a2, b1);
            fma2(acc[3][0], a3, b0); fma2(acc[3][1], a3, b1);
        }
        __syncthreads();
    }

    #pragma unroll
    for (int i = 0; i < 4; i++) {
        int row = rbase + tm4 + i;
        float* dst = &g_X[(long long)row * NHID + cbase + tn4];
        *(ull*)(dst)     = acc[i][0];
        *(ull*)(dst + 2) = acc[i][1];
    }
}

// =====================================================================
// Phase 2: recurrence. 128 CTAs x 256 threads, 2 batch rows/CTA,
// thread j owns column j for both rows.
// Wh rows 0..95 in smem (96 KB), rows 96..255 in registers (160 regs).
// h double-buffered in smem -> ONE barrier per step.
// =====================================================================
#define SQ 24   // smem k4-groups  (rows 0..95)
#define RQ 40   // reg  k4-groups  (rows 96..255)
#define P2_SMEM (SQ * 256 * 16 + 2 * 512 * 4)

__global__ void __launch_bounds__(256, 1) rnn_kernel(
    const float* __restrict__ Wh,
    const float* __restrict__ fcw,
    const float* __restrict__ fcb,
    float* __restrict__ out)
{
    extern __shared__ __align__(16) char smem[];
    ulonglong2* WhS = (ulonglong2*)smem;                    // [SQ*256]
    float*      hb  = (float*)(smem + SQ * 256 * 16);       // [2][2][256]

    const int j  = threadIdx.x;            // column 0..255
    const int r0 = blockIdx.x * 2;
    const int r1 = r0 + 1;

    // Wh rows 0..95 -> smem, packed float4-over-k: WhS[q][c] = Wh[4q..4q+3][c]
    for (int i = j; i < SQ * 256; i += 256) {
        int q = i >> 8, c = i & 255, kr = 4 * q;
        float4 v = make_float4(Wh[kr * NHID + c],       Wh[(kr + 1) * NHID + c],
                               Wh[(kr + 2) * NHID + c], Wh[(kr + 3) * NHID + c]);
        ((float4*)smem)[i] = v;
    }
    // Wh rows 96..255, col j -> registers
    ulonglong2 whr[RQ];
    #pragma unroll
    for (int q = 0; q < RQ; q++) {
        int kr = 96 + 4 * q;
        whr[q].x = pack2(Wh[kr * NHID + j],       Wh[(kr + 1) * NHID + j]);
        whr[q].y = pack2(Wh[(kr + 2) * NHID + j], Wh[(kr + 3) * NHID + j]);
    }
    hb[j] = 0.f; hb[256 + j] = 0.f;   // h0 = 0 in buffer 0
    __syncthreads();

    float x0 = g_X[r0 * NHID + j];
    float x1 = g_X[r1 * NHID + j];

    int buf = 0;
    for (int t = 0; t < SEQLEN; t++) {
        const ulonglong2* H0 = (const ulonglong2*)(hb + buf * 512);
        const ulonglong2* H1 = H0 + 64;

        ull a0 = 0, a1 = 0;
        #pragma unroll 8
        for (int q = 0; q < SQ; q++) {
            ulonglong2 w  = WhS[q * 256 + j];
            ulonglong2 h0 = H0[q];
            ulonglong2 h1 = H1[q];
            fma2(a0, h0.x, w.x); fma2(a0, h0.y, w.y);
            fma2(a1, h1.x, w.x); fma2(a1, h1.y, w.y);
        }
        #pragma unroll
        for (int q = 0; q < RQ; q++) {
            ulonglong2 h0 = H0[SQ + q];
            ulonglong2 h1 = H1[SQ + q];
            fma2(a0, h0.x, whr[q].x); fma2(a0, h0.y, whr[q].y);
            fma2(a1, h1.x, whr[q].x); fma2(a1, h1.y, whr[q].y);
        }

        float2 s0 = unpack2(a0), s1 = unpack2(a1);
        float hn0 = sigmoidf(x0 + s0.x + s0.y);
        float hn1 = sigmoidf(x1 + s1.x + s1.y);

        if (t + 1 < SEQLEN) {
            const float* xp = g_X + (t + 1) * (BATCHN * NHID);
            x0 = xp[r0 * NHID + j];
            x1 = xp[r1 * NHID + j];
        }

        int nb = buf ^ 1;
        hb[nb * 512 + j]       = hn0;
        hb[nb * 512 + 256 + j] = hn1;
        __syncthreads();
        buf = nb;
    }

    float hf0 = hb[buf * 512 + j];
    float hf1 = hb[buf * 512 + 256 + j];
    out[256 + r0 * NHID + j] = hf0;
    out[256 + r1 * NHID + j] = hf1;

    // sig = sigmoid(h @ fc_w + fc_b): warp 0 -> row r0, warp 1 -> row r1
    int w = j >> 5, l = j & 31;
    if (w < 2) {
        float s = 0.f;
        #pragma unroll
        for (int q = 0; q < 8; q++)
            s += hb[buf * 512 + w * 256 + l + q * 32] * fcw[l + q * 32];
        #pragma unroll
        for (int o = 16; o; o >>= 1)
            s += __shfl_xor_sync(0xffffffffu, s, o);
        if (l == 0)
            out[r0 + w] = sigmoidf(s + fcb[0]);
    }
}

// =====================================================================
extern "C" void kernel_launch(void* const* d_in, const int* in_sizes, int n_in,
                              void* d_out, int out_size)
{
    const int*   words = (const int*)  d_in[0];
    const float* emb   = (const float*)d_in[1];
    const float* Wi    = (const float*)d_in[2];
    const float* Wh    = (const float*)d_in[3];
    const float* fcw   = (const float*)d_in[4];
    const float* fcb   = (const float*)d_in[5];
    float*       out   = (float*)d_out;

    cudaFuncSetAttribute(rnn_kernel, cudaFuncAttributeMaxDynamicSharedMemorySize, P2_SMEM);

    x_gemm_kernel<<<dim3((SEQLEN * BATCHN) / 64, NHID / 64), 256>>>(words, emb, Wi);
    rnn_kernel<<<BATCHN / 2, 256, P2_SMEM>>>(Wh, fcw, fcb, out);
}

// round 5
// speedup vs baseline: 1.1542x; 1.1311x over previous
#include <cuda_runtime.h>
#include <cstdint>

#define BATCHN 256
#define SEQLEN 512
#define NEMB   300
#define NHID   256

typedef unsigned long long ull;

// ---------- packed f32x2 helpers (sm_103a FFMA2 path) ----------
__device__ __forceinline__ void fma2(ull &d, ull a, ull b) {
    asm("fma.rn.f32x2 %0, %1, %2, %0;" : "+l"(d) : "l"(a), "l"(b));
}
__device__ __forceinline__ ull pack2(float x, float y) {
    ull r; asm("mov.b64 %0, {%1, %2};" : "=l"(r) : "f"(x), "f"(y)); return r;
}
__device__ __forceinline__ float2 unpack2(ull v) {
    float2 r; asm("mov.b64 {%0, %1}, %2;" : "=f"(r.x), "=f"(r.y) : "l"(v)); return r;
}
__device__ __forceinline__ float sigmoidf(float z) {
    return 1.0f / (1.0f + __expf(-z));
}

// Scratch: X[t][b][h] = (emb[words[b][t]] @ Wi), time-major. 128 MB device global.
__device__ float g_X[SEQLEN * BATCHN * NHID];

// =====================================================================
// Phase 1: X = gather(emb) @ Wi.  Rows r = t*256 + b (131072), cols 256.
// 128x64 tiles, K in 15 chunks of 20. Micro-tile 8x4.
// A pre-DUPLICATED in smem as (a,a) ull -> inner loop is MOV-FREE:
//   per k: 4x LDS.128 (A, broadcast, 1 wf each) + 1x LDS.128 (B pairs, 2 wf)
//          + 16 fma2  => issue 42 < crossbar 48 < fma 64 cyc/SM-k. fma-bound.
// acc = 16 ull = 32 regs. occ 2.
// =====================================================================
__global__ __launch_bounds__(256, 2) void x_gemm_kernel(
    const int* __restrict__ words,
    const float* __restrict__ emb,
    const float* __restrict__ Wi)
{
    __shared__ int wsm[128];
    __shared__ __align__(16) ull   Adup[20][128];  // (a,a) duplicated, 20 KB
    __shared__ __align__(16) float Bs[20][64];     // 5 KB

    const int tid   = threadIdx.x;
    const int rbase = blockIdx.x * 128;
    const int cbase = blockIdx.y * 64;

    if (tid < 128) {
        int r = rbase + tid;
        wsm[tid] = words[(r & 255) * SEQLEN + (r >> 8)];
    }
    __syncthreads();

    const int tm8 = (tid >> 4) * 8;   // rows tm8 .. tm8+7  (16 groups)
    const int tn4 = (tid & 15) * 4;   // cols tn4 .. tn4+3  (16 groups)

    ull acc[8][2];
    #pragma unroll
    for (int i = 0; i < 8; i++) { acc[i][0] = 0ULL; acc[i][1] = 0ULL; }

    // prefetch regs: A chunk = 128 rows x 20 k = 1280 float2 (5/thread)
    //                B chunk = 20 k x 64 cols = 1280 floats    (5/thread)
    float2 pa[5];
    float  pb[5];

    #pragma unroll
    for (int l = 0; l < 5; l++) {
        int e = tid + l * 256;
        int m = e / 10, kp = e % 10;
        pa[l] = *(const float2*)&emb[(long long)wsm[m] * NEMB + 2 * kp];
        int k = e >> 6, n = e & 63;
        pb[l] = Wi[k * NHID + cbase + n];
    }

    for (int c = 0; c < 15; c++) {
        // commit prefetched chunk to smem (A duplicated to (a,a))
        #pragma unroll
        for (int l = 0; l < 5; l++) {
            int e = tid + l * 256;
            int m = e / 10, kp = e % 10;
            Adup[2 * kp][m]     = pack2(pa[l].x, pa[l].x);
            Adup[2 * kp + 1][m] = pack2(pa[l].y, pa[l].y);
            int k = e >> 6, n = e & 63;
            Bs[k][n] = pb[l];
        }
        __syncthreads();

        // prefetch next chunk (LDG latency hides under compute)
        if (c + 1 < 15) {
            int k0 = (c + 1) * 20;
            #pragma unroll
            for (int l = 0; l < 5; l++) {
                int e = tid + l * 256;
                int m = e / 10, kp = e % 10;
                pa[l] = *(const float2*)&emb[(long long)wsm[m] * NEMB + k0 + 2 * kp];
                int k = e >> 6, n = e & 63;
                pb[l] = Wi[(k0 + k) * NHID + cbase + n];
            }
        }

        #pragma unroll
        for (int k = 0; k < 20; k++) {
            ulonglong2 a01 = *(const ulonglong2*)&Adup[k][tm8 + 0];
            ulonglong2 a23 = *(const ulonglong2*)&Adup[k][tm8 + 2];
            ulonglong2 a45 = *(const ulonglong2*)&Adup[k][tm8 + 4];
            ulonglong2 a67 = *(const ulonglong2*)&Adup[k][tm8 + 6];
            ulonglong2 b   = *(const ulonglong2*)&Bs[k][tn4];  // (b0,b1),(b2,b3)
            fma2(acc[0][0], a01.x, b.x); fma2(acc[0][1], a01.x, b.y);
            fma2(acc[1][0], a01.y, b.x); fma2(acc[1][1], a01.y, b.y);
            fma2(acc[2][0], a23.x, b.x); fma2(acc[2][1], a23.x, b.y);
            fma2(acc[3][0], a23.y, b.x); fma2(acc[3][1], a23.y, b.y);
            fma2(acc[4][0], a45.x, b.x); fma2(acc[4][1], a45.x, b.y);
            fma2(acc[5][0], a45.y, b.x); fma2(acc[5][1], a45.y, b.y);
            fma2(acc[6][0], a67.x, b.x); fma2(acc[6][1], a67.x, b.y);
            fma2(acc[7][0], a67.y, b.x); fma2(acc[7][1], a67.y, b.y);
        }
        __syncthreads();
    }

    #pragma unroll
    for (int m = 0; m < 8; m++) {
        int row = rbase + tm8 + m;
        float* dst = &g_X[(long long)row * NHID + cbase + tn4];
        *(ulonglong2*)dst = make_ulonglong2(acc[m][0], acc[m][1]);
    }
}

// =====================================================================
// Phase 2: recurrence. 128 CTAs x 256 threads, 2 batch rows/CTA,
// thread j owns column j for both rows.
// Wh rows 0..95 in smem (96 KB), rows 96..255 in registers (160 regs).
// h double-buffered in smem -> ONE barrier per step.
// =====================================================================
#define SQ 24   // smem k4-groups  (rows 0..95)
#define RQ 40   // reg  k4-groups  (rows 96..255)
#define P2_SMEM (SQ * 256 * 16 + 2 * 512 * 4)

__global__ void __launch_bounds__(256, 1) rnn_kernel(
    const float* __restrict__ Wh,
    const float* __restrict__ fcw,
    const float* __restrict__ fcb,
    float* __restrict__ out)
{
    extern __shared__ __align__(16) char smem[];
    ulonglong2* WhS = (ulonglong2*)smem;                    // [SQ*256]
    float*      hb  = (float*)(smem + SQ * 256 * 16);       // [2][2][256]

    const int j  = threadIdx.x;            // column 0..255
    const int r0 = blockIdx.x * 2;
    const int r1 = r0 + 1;

    // Wh rows 0..95 -> smem, packed float4-over-k: WhS[q][c] = Wh[4q..4q+3][c]
    for (int i = j; i < SQ * 256; i += 256) {
        int q = i >> 8, c = i & 255, kr = 4 * q;
        float4 v = make_float4(Wh[kr * NHID + c],       Wh[(kr + 1) * NHID + c],
                               Wh[(kr + 2) * NHID + c], Wh[(kr + 3) * NHID + c]);
        ((float4*)smem)[i] = v;
    }
    // Wh rows 96..255, col j -> registers
    ulonglong2 whr[RQ];
    #pragma unroll
    for (int q = 0; q < RQ; q++) {
        int kr = 96 + 4 * q;
        whr[q].x = pack2(Wh[kr * NHID + j],       Wh[(kr + 1) * NHID + j]);
        whr[q].y = pack2(Wh[(kr + 2) * NHID + j], Wh[(kr + 3) * NHID + j]);
    }
    hb[j] = 0.f; hb[256 + j] = 0.f;   // h0 = 0 in buffer 0
    __syncthreads();

    float x0 = g_X[r0 * NHID + j];
    float x1 = g_X[r1 * NHID + j];

    int buf = 0;
    for (int t = 0; t < SEQLEN; t++) {
        const ulonglong2* H0 = (const ulonglong2*)(hb + buf * 512);
        const ulonglong2* H1 = H0 + 64;

        ull a0 = 0, a1 = 0;
        #pragma unroll 8
        for (int q = 0; q < SQ; q++) {
            ulonglong2 w  = WhS[q * 256 + j];
            ulonglong2 h0 = H0[q];
            ulonglong2 h1 = H1[q];
            fma2(a0, h0.x, w.x); fma2(a0, h0.y, w.y);
            fma2(a1, h1.x, w.x); fma2(a1, h1.y, w.y);
        }
        #pragma unroll
        for (int q = 0; q < RQ; q++) {
            ulonglong2 h0 = H0[SQ + q];
            ulonglong2 h1 = H1[SQ + q];
            fma2(a0, h0.x, whr[q].x); fma2(a0, h0.y, whr[q].y);
            fma2(a1, h1.x, whr[q].x); fma2(a1, h1.y, whr[q].y);
        }

        float2 s0 = unpack2(a0), s1 = unpack2(a1);
        float hn0 = sigmoidf(x0 + s0.x + s0.y);
        float hn1 = sigmoidf(x1 + s1.x + s1.y);

        if (t + 1 < SEQLEN) {
            const float* xp = g_X + (t + 1) * (BATCHN * NHID);
            x0 = xp[r0 * NHID + j];
            x1 = xp[r1 * NHID + j];
        }

        int nb = buf ^ 1;
        hb[nb * 512 + j]       = hn0;
        hb[nb * 512 + 256 + j] = hn1;
        __syncthreads();
        buf = nb;
    }

    float hf0 = hb[buf * 512 + j];
    float hf1 = hb[buf * 512 + 256 + j];
    out[256 + r0 * NHID + j] = hf0;
    out[256 + r1 * NHID + j] = hf1;

    // sig = sigmoid(h @ fc_w + fc_b): warp 0 -> row r0, warp 1 -> row r1
    int w = j >> 5, l = j & 31;
    if (w < 2) {
        float s = 0.f;
        #pragma unroll
        for (int q = 0; q < 8; q++)
            s += hb[buf * 512 + w * 256 + l + q * 32] * fcw[l + q * 32];
        #pragma unroll
        for (int o = 16; o; o >>= 1)
            s += __shfl_xor_sync(0xffffffffu, s, o);
        if (l == 0)
            out[r0 + w] = sigmoidf(s + fcb[0]);
    }
}

// =====================================================================
extern "C" void kernel_launch(void* const* d_in, const int* in_sizes, int n_in,
                              void* d_out, int out_size)
{
    const int*   words = (const int*)  d_in[0];
    const float* emb   = (const float*)d_in[1];
    const float* Wi    = (const float*)d_in[2];
    const float* Wh    = (const float*)d_in[3];
    const float* fcw   = (const float*)d_in[4];
    const float* fcb   = (const float*)d_in[5];
    float*       out   = (float*)d_out;

    cudaFuncSetAttribute(rnn_kernel, cudaFuncAttributeMaxDynamicSharedMemorySize, P2_SMEM);

    x_gemm_kernel<<<dim3((SEQLEN * BATCHN) / 128, NHID / 64), 256>>>(words, emb, Wi);
    rnn_kernel<<<BATCHN / 2, 256, P2_SMEM>>>(Wh, fcw, fcb, out);
}

// round 7
// speedup vs baseline: 1.7526x; 1.5185x over previous
#include <cuda_runtime.h>
#include <cuda_bf16.h>
#include <cstdint>

#define BATCHN 256
#define SEQLEN 512
#define NEMB   300
#define NHID   256
#define EMBS   320          // padded K (5 chunks of 64)

typedef unsigned long long ull;

// ---------- packed f32x2 helpers (rnn path) ----------
__device__ __forceinline__ void fma2(ull &d, ull a, ull b) {
    asm("fma.rn.f32x2 %0, %1, %2, %0;" : "+l"(d) : "l"(a), "l"(b));
}
__device__ __forceinline__ ull pack2(float x, float y) {
    ull r; asm("mov.b64 %0, {%1, %2};" : "=l"(r) : "f"(x), "f"(y)); return r;
}
__device__ __forceinline__ float2 unpack2(ull v) {
    float2 r; asm("mov.b64 {%0, %1}, %2;" : "=f"(r.x), "=f"(r.y) : "l"(v)); return r;
}
__device__ __forceinline__ float sigmoidf(float z) {
    return 1.0f / (1.0f + __expf(-z));
}

// ---------- HMMA / ldmatrix / cp.async helpers (base-target features) ----------
__device__ __forceinline__ uint32_t smem_u32(const void* p) {
    uint32_t a;
    asm("{ .reg .u64 t; cvta.to.shared.u64 t, %1; cvt.u32.u64 %0, t; }" : "=r"(a) : "l"(p));
    return a;
}
__device__ __forceinline__ void ldm4(uint32_t* r, uint32_t addr) {
    asm volatile("ldmatrix.sync.aligned.m8n8.x4.shared.b16 {%0,%1,%2,%3}, [%4];"
                 : "=r"(r[0]), "=r"(r[1]), "=r"(r[2]), "=r"(r[3]) : "r"(addr));
}
__device__ __forceinline__ void mma16816(float* d, const uint32_t* a, uint32_t b0, uint32_t b1) {
    asm volatile(
        "mma.sync.aligned.m16n8k16.row.col.f32.bf16.bf16.f32 "
        "{%0,%1,%2,%3}, {%4,%5,%6,%7}, {%8,%9}, {%0,%1,%2,%3};"
        : "+f"(d[0]), "+f"(d[1]), "+f"(d[2]), "+f"(d[3])
        : "r"(a[0]), "r"(a[1]), "r"(a[2]), "r"(a[3]), "r"(b0), "r"(b1));
}
#define CP16(dst, src) asm volatile("cp.async.cg.shared.global [%0], [%1], 16;" :: "r"(dst), "l"(src) : "memory")
#define CPCOMMIT()     asm volatile("cp.async.commit_group;" ::: "memory")
#define CPWAIT1()      asm volatile("cp.async.wait_group 1;" ::: "memory")
#define CPWAIT0()      asm volatile("cp.async.wait_group 0;" ::: "memory")

// ---------- device scratch ----------
__device__ float g_X[SEQLEN * BATCHN * NHID];                 // 128 MB
__device__ __nv_bfloat16 g_emb_hi[(size_t)50257 * EMBS];      // 32 MB
__device__ __nv_bfloat16 g_emb_lo[(size_t)50257 * EMBS];      // 32 MB
__device__ __nv_bfloat16 g_wt_hi[256 * EMBS];                 // Wi^T hi  [n][k]
__device__ __nv_bfloat16 g_wt_lo[256 * EMBS];                 // Wi^T lo  [n][k]

// =====================================================================
// Split-convert: fp32 -> (hi, lo) bf16, K zero-padded to 320.
// =====================================================================
__global__ __launch_bounds__(128) void convert_emb_kernel(const float* __restrict__ emb)
{
    const int e = blockIdx.x, tid = threadIdx.x;
    const float* src = emb + (size_t)e * NEMB;
    __nv_bfloat16* hi = g_emb_hi + (size_t)e * EMBS;
    __nv_bfloat16* lo = g_emb_lo + (size_t)e * EMBS;
    for (int k = tid; k < EMBS; k += 128) {
        float v = (k < NEMB) ? src[k] : 0.f;
        __nv_bfloat16 h = __float2bfloat16(v);
        hi[k] = h;
        lo[k] = __float2bfloat16(v - __bfloat162float(h));
    }
}
__global__ __launch_bounds__(128) void convert_wi_kernel(const float* __restrict__ Wi)
{
    const int n = blockIdx.x, tid = threadIdx.x;
    for (int k = tid; k < EMBS; k += 128) {
        float v = (k < NEMB) ? Wi[k * NHID + n] : 0.f;
        __nv_bfloat16 h = __float2bfloat16(v);
        g_wt_hi[n * EMBS + k] = h;
        g_wt_lo[n * EMBS + k] = __float2bfloat16(v - __bfloat162float(h));
    }
}

// =====================================================================
// Phase 1: X = gather(emb) @ Wi via 3-GEMM bf16 split on HMMA (mma.sync).
// CTA 128x128, 512 thr / 16 warps (4x4), warp tile 32x32.
// K = 5 chunks of 64, cp.async double-buffered smem, 144B row stride.
// =====================================================================
#define RSTRIDE 144                       // 72 bf16 per row, conflict-free
#define AHI_OFF 0
#define ALO_OFF 18432
#define BHI_OFF 36864
#define BLO_OFF 55296
#define BUFSZ   73728
#define WS_OFF  (2 * BUFSZ)
#define G7_SMEM (2 * BUFSZ + 512)

__global__ void __launch_bounds__(512, 1) x_gemm_hmma(const int* __restrict__ words)
{
    extern __shared__ __align__(16) char dsm[];
    const uint32_t smb = smem_u32(dsm);
    int* wsm = (int*)(dsm + WS_OFF);

    const int tid = threadIdx.x, wid = tid >> 5, lid = tid & 31;
    const int rbase = blockIdx.x * 128;
    const int cbase = blockIdx.y * 128;

    if (tid < 128) {
        int r = rbase + tid;
        wsm[tid] = words[(r & 255) * SEQLEN + (r >> 8)];
    }
    __syncthreads();

    // cp.async issue of chunk c into buffer buf
    auto issue = [&](int c, int buf) {
        const uint32_t base = smb + buf * BUFSZ;
        #pragma unroll
        for (int q = 0; q < 2; q++) {
            int idx = tid + q * 512;            // 0..1023
            int row = idx >> 3, seg = idx & 7;
            uint32_t doff = (uint32_t)(row * RSTRIDE + seg * 16);
            size_t aoff = (size_t)wsm[row] * EMBS + c * 64 + seg * 8;
            CP16(base + AHI_OFF + doff, (const char*)(g_emb_hi + aoff));
            CP16(base + ALO_OFF + doff, (const char*)(g_emb_lo + aoff));
            size_t boff = (size_t)(cbase + row) * EMBS + c * 64 + seg * 8;
            CP16(base + BHI_OFF + doff, (const char*)(g_wt_hi + boff));
            CP16(base + BLO_OFF + doff, (const char*)(g_wt_lo + boff));
        }
        CPCOMMIT();
    };

    const int wm = (wid >> 2) * 32;       // warp row base (0..96)
    const int wn = (wid & 3) * 32;        // warp col base (0..96)

    // per-lane ldmatrix offsets (x4 layout)
    // A mats: (row-lo,k-lo)(row-hi,k-lo)(row-lo,k-hi)(row-hi,k-hi)
    const uint32_t a_lane =
        (uint32_t)((wm + (lid & 7) + ((lid >> 3) & 1) * 8) * RSTRIDE + ((lid >> 4) & 1) * 16);
    // B mats: (n-tile0,k-lo)(n-tile0,k-hi)(n-tile1,k-lo)(n-tile1,k-hi)
    const uint32_t b_lane =
        (uint32_t)((wn + (lid & 7) + ((lid >> 4) & 1) * 8) * RSTRIDE + ((lid >> 3) & 1) * 16);

    float acc[2][4][4];
    #pragma unroll
    for (int m = 0; m < 2; m++)
        #pragma unroll
        for (int j = 0; j < 4; j++)
            #pragma unroll
            for (int e = 0; e < 4; e++) acc[m][j][e] = 0.f;

    issue(0, 0);

    for (int c = 0; c < 5; c++) {
        if (c + 1 < 5) { issue(c + 1, (c + 1) & 1); CPWAIT1(); }
        else          { CPWAIT0(); }
        __syncthreads();

        const uint32_t bb = smb + (c & 1) * BUFSZ;
        #pragma unroll
        for (int ks = 0; ks < 4; ks++) {           // k16 steps within chunk
            const uint32_t ko = ks * 32;           // 16 elems * 2 B
            uint32_t ah[2][4], al[2][4], bh[2][4], bl[2][4];
            #pragma unroll
            for (int mt = 0; mt < 2; mt++) {
                ldm4(ah[mt], bb + AHI_OFF + a_lane + mt * (16 * RSTRIDE) + ko);
                ldm4(al[mt], bb + ALO_OFF + a_lane + mt * (16 * RSTRIDE) + ko);
            }
            #pragma unroll
            for (int np = 0; np < 2; np++) {
                ldm4(bh[np], bb + BHI_OFF + b_lane + np * (16 * RSTRIDE) + ko);
                ldm4(bl[np], bb + BLO_OFF + b_lane + np * (16 * RSTRIDE) + ko);
            }
            // hi*hi
            #pragma unroll
            for (int mt = 0; mt < 2; mt++)
                #pragma unroll
                for (int j = 0; j < 4; j++)
                    mma16816(acc[mt][j], ah[mt], bh[j >> 1][(j & 1) * 2], bh[j >> 1][(j & 1) * 2 + 1]);
            // lo*hi
            #pragma unroll
            for (int mt = 0; mt < 2; mt++)
                #pragma unroll
                for (int j = 0; j < 4; j++)
                    mma16816(acc[mt][j], al[mt], bh[j >> 1][(j & 1) * 2], bh[j >> 1][(j & 1) * 2 + 1]);
            // hi*lo
            #pragma unroll
            for (int mt = 0; mt < 2; mt++)
                #pragma unroll
                for (int j = 0; j < 4; j++)
                    mma16816(acc[mt][j], ah[mt], bl[j >> 1][(j & 1) * 2], bl[j >> 1][(j & 1) * 2 + 1]);
        }
        __syncthreads();
    }

    // epilogue: D fragment -> g_X (fp32)
    const int g  = lid >> 2;
    const int i2 = (lid & 3) * 2;
    #pragma unroll
    for (int mt = 0; mt < 2; mt++) {
        #pragma unroll
        for (int j = 0; j < 4; j++) {
            int row = rbase + wm + mt * 16 + g;
            int col = cbase + wn + j * 8 + i2;
            *(float2*)&g_X[(size_t)row * NHID + col] =
                make_float2(acc[mt][j][0], acc[mt][j][1]);
            *(float2*)&g_X[(size_t)(row + 8) * NHID + col] =
                make_float2(acc[mt][j][2], acc[mt][j][3]);
        }
    }
}

// =====================================================================
// Phase 2: recurrence (unchanged R2 best). 128 CTAs x 256 threads.
// =====================================================================
#define SQ 24
#define RQ 40
#define P2_SMEM (SQ * 256 * 16 + 2 * 512 * 4)

__global__ void __launch_bounds__(256, 1) rnn_kernel(
    const float* __restrict__ Wh,
    const float* __restrict__ fcw,
    const float* __restrict__ fcb,
    float* __restrict__ out)
{
    extern __shared__ __align__(16) char smem[];
    ulonglong2* WhS = (ulonglong2*)smem;
    float*      hb  = (float*)(smem + SQ * 256 * 16);

    const int j  = threadIdx.x;
    const int r0 = blockIdx.x * 2;
    const int r1 = r0 + 1;

    for (int i = j; i < SQ * 256; i += 256) {
        int q = i >> 8, c = i & 255, kr = 4 * q;
        float4 v = make_float4(Wh[kr * NHID + c],       Wh[(kr + 1) * NHID + c],
                               Wh[(kr + 2) * NHID + c], Wh[(kr + 3) * NHID + c]);
        ((float4*)smem)[i] = v;
    }
    ulonglong2 whr[RQ];
    #pragma unroll
    for (int q = 0; q < RQ; q++) {
        int kr = 96 + 4 * q;
        whr[q].x = pack2(Wh[kr * NHID + j],       Wh[(kr + 1) * NHID + j]);
        whr[q].y = pack2(Wh[(kr + 2) * NHID + j], Wh[(kr + 3) * NHID + j]);
    }
    hb[j] = 0.f; hb[256 + j] = 0.f;
    __syncthreads();

    float x0 = g_X[r0 * NHID + j];
    float x1 = g_X[r1 * NHID + j];

    int buf = 0;
    for (int t = 0; t < SEQLEN; t++) {
        const ulonglong2* H0 = (const ulonglong2*)(hb + buf * 512);
        const ulonglong2* H1 = H0 + 64;

        ull a0 = 0, a1 = 0;
        #pragma unroll 8
        for (int q = 0; q < SQ; q++) {
            ulonglong2 w  = WhS[q * 256 + j];
            ulonglong2 h0 = H0[q];
            ulonglong2 h1 = H1[q];
            fma2(a0, h0.x, w.x); fma2(a0, h0.y, w.y);
            fma2(a1, h1.x, w.x); fma2(a1, h1.y, w.y);
        }
        #pragma unroll
        for (int q = 0; q < RQ; q++) {
            ulonglong2 h0 = H0[SQ + q];
            ulonglong2 h1 = H1[SQ + q];
            fma2(a0, h0.x, whr[q].x); fma2(a0, h0.y, whr[q].y);
            fma2(a1, h1.x, whr[q].x); fma2(a1, h1.y, whr[q].y);
        }

        float2 s0 = unpack2(a0), s1 = unpack2(a1);
        float hn0 = sigmoidf(x0 + s0.x + s0.y);
        float hn1 = sigmoidf(x1 + s1.x + s1.y);

        if (t + 1 < SEQLEN) {
            const float* xp = g_X + (t + 1) * (BATCHN * NHID);
            x0 = xp[r0 * NHID + j];
            x1 = xp[r1 * NHID + j];
        }

        int nb = buf ^ 1;
        hb[nb * 512 + j]       = hn0;
        hb[nb * 512 + 256 + j] = hn1;
        __syncthreads();
        buf = nb;
    }

    out[256 + r0 * NHID + j] = hb[buf * 512 + j];
    out[256 + r1 * NHID + j] = hb[buf * 512 + 256 + j];

    int w = j >> 5, l = j & 31;
    if (w < 2) {
        float s = 0.f;
        #pragma unroll
        for (int q = 0; q < 8; q++)
            s += hb[buf * 512 + w * 256 + l + q * 32] * fcw[l + q * 32];
        #pragma unroll
        for (int o = 16; o; o >>= 1)
            s += __shfl_xor_sync(0xffffffffu, s, o);
        if (l == 0)
            out[r0 + w] = sigmoidf(s + fcb[0]);
    }
}

// =====================================================================
extern "C" void kernel_launch(void* const* d_in, const int* in_sizes, int n_in,
                              void* d_out, int out_size)
{
    const int*   words = (const int*)  d_in[0];
    const float* emb   = (const float*)d_in[1];
    const float* Wi    = (const float*)d_in[2];
    const float* Wh    = (const float*)d_in[3];
    const float* fcw   = (const float*)d_in[4];
    const float* fcb   = (const float*)d_in[5];
    float*       out   = (float*)d_out;

    cudaFuncSetAttribute(x_gemm_hmma, cudaFuncAttributeMaxDynamicSharedMemorySize, G7_SMEM);
    cudaFuncSetAttribute(rnn_kernel, cudaFuncAttributeMaxDynamicSharedMemorySize, P2_SMEM);

    convert_emb_kernel<<<50257, 128>>>(emb);
    convert_wi_kernel<<<NHID, 128>>>(Wi);
    x_gemm_hmma<<<dim3((SEQLEN * BATCHN) / 128, NHID / 128), 512, G7_SMEM>>>(words);
    rnn_kernel<<<BATCHN / 2, 256, P2_SMEM>>>(Wh, fcw, fcb, out);
}

// round 8
// speedup vs baseline: 1.9968x; 1.1393x over previous
#include <cuda_runtime.h>
#include <cuda_bf16.h>
#include <cstdint>

#define BATCHN 256
#define SEQLEN 512
#define NEMB   300
#define NHID   256
#define EMBS   320          // padded K (5 chunks of 64)
#define M_PAD  50304        // vocab rows padded to 128

typedef unsigned long long ull;

// ---------- packed f32x2 helpers (rnn path) ----------
__device__ __forceinline__ void fma2(ull &d, ull a, ull b) {
    asm("fma.rn.f32x2 %0, %1, %2, %0;" : "+l"(d) : "l"(a), "l"(b));
}
__device__ __forceinline__ ull pack2(float x, float y) {
    ull r; asm("mov.b64 %0, {%1, %2};" : "=l"(r) : "f"(x), "f"(y)); return r;
}
__device__ __forceinline__ float2 unpack2(ull v) {
    float2 r; asm("mov.b64 {%0, %1}, %2;" : "=f"(r.x), "=f"(r.y) : "l"(v)); return r;
}
__device__ __forceinline__ float sigmoidf(float z) {
    return 1.0f / (1.0f + __expf(-z));
}

// ---------- HMMA / ldmatrix / cp.async helpers ----------
__device__ __forceinline__ uint32_t smem_u32(const void* p) {
    uint32_t a;
    asm("{ .reg .u64 t; cvta.to.shared.u64 t, %1; cvt.u32.u64 %0, t; }" : "=r"(a) : "l"(p));
    return a;
}
__device__ __forceinline__ void ldm4(uint32_t* r, uint32_t addr) {
    asm volatile("ldmatrix.sync.aligned.m8n8.x4.shared.b16 {%0,%1,%2,%3}, [%4];"
                 : "=r"(r[0]), "=r"(r[1]), "=r"(r[2]), "=r"(r[3]) : "r"(addr));
}
__device__ __forceinline__ void mma16816(float* d, const uint32_t* a, uint32_t b0, uint32_t b1) {
    asm volatile(
        "mma.sync.aligned.m16n8k16.row.col.f32.bf16.bf16.f32 "
        "{%0,%1,%2,%3}, {%4,%5,%6,%7}, {%8,%9}, {%0,%1,%2,%3};"
        : "+f"(d[0]), "+f"(d[1]), "+f"(d[2]), "+f"(d[3])
        : "r"(a[0]), "r"(a[1]), "r"(a[2]), "r"(a[3]), "r"(b0), "r"(b1));
}
__device__ __forceinline__ uint32_t bfpair(float a, float b) {
    __nv_bfloat162 t = __floats2bfloat162_rn(a, b);
    return *(uint32_t*)&t;
}
__device__ __forceinline__ void sts128(uint32_t addr, uint4 v) {
    asm volatile("st.shared.v4.b32 [%0], {%1,%2,%3,%4};"
                 :: "r"(addr), "r"(v.x), "r"(v.y), "r"(v.z), "r"(v.w) : "memory");
}
#define CP16(dst, src) asm volatile("cp.async.cg.shared.global [%0], [%1], 16;" :: "r"(dst), "l"(src) : "memory")
#define CPCOMMIT()     asm volatile("cp.async.commit_group;" ::: "memory")
#define CPWAIT1()      asm volatile("cp.async.wait_group 1;" ::: "memory")
#define CPWAIT0()      asm volatile("cp.async.wait_group 0;" ::: "memory")

// ---------- device scratch ----------
__device__ float g_proj[(size_t)M_PAD * NHID];                // 51.5 MB: proj = emb @ Wi
__device__ __nv_bfloat16 g_wt_hi[256 * EMBS];                 // Wi^T hi  [n][k]
__device__ __nv_bfloat16 g_wt_lo[256 * EMBS];                 // Wi^T lo  [n][k]

// =====================================================================
// Wi^T split-convert: fp32 -> (hi, lo) bf16, K zero-padded to 320.
// =====================================================================
__global__ __launch_bounds__(128) void convert_wi_kernel(const float* __restrict__ Wi)
{
    const int n = blockIdx.x, tid = threadIdx.x;
    for (int k = tid; k < EMBS; k += 128) {
        float v = (k < NEMB) ? Wi[k * NHID + n] : 0.f;
        __nv_bfloat16 h = __float2bfloat16(v);
        g_wt_hi[n * EMBS + k] = h;
        g_wt_lo[n * EMBS + k] = __float2bfloat16(v - __bfloat162float(h));
    }
}

// =====================================================================
// proj = emb @ Wi via 3-GEMM bf16 split on HMMA. CTA 128x128, 512 thr.
// A (emb) converted fp32->hi/lo ON THE FLY; B (Wi^T hi/lo) via cp.async
// double-buffer. K = 5 chunks of 64. 144B row stride, conflict-free ldmatrix.
// =====================================================================
#define RSTRIDE 144
#define AHI_OFF 0
#define ALO_OFF 18432
#define BHI_OFF 36864
#define BLO_OFF 55296
#define BUFSZ   73728
#define G8_SMEM (2 * BUFSZ + 64)

__global__ void __launch_bounds__(512, 1) proj_gemm(const float* __restrict__ emb)
{
    extern __shared__ __align__(16) char dsm[];
    const uint32_t smb = smem_u32(dsm);

    const int tid = threadIdx.x, wid = tid >> 5, lid = tid & 31;
    const int rbase = blockIdx.x * 128;
    const int cbase = blockIdx.y * 128;

    // A staging: thread -> row rbase+(tid>>2), quarter (tid&3) of 16 floats
    const int arow  = rbase + (tid >> 2);
    const int arowg = (arow < 50257) ? arow : 50256;      // clamp OOB pad rows
    const int aq    = (tid & 3) * 16;                     // k offset within chunk
    float4 af[4];

    auto lda = [&](int c) {
        #pragma unroll
        for (int i = 0; i < 4; i++) {
            int k = c * 64 + aq + i * 4;
            af[i] = (k < NEMB) ? *(const float4*)&emb[(size_t)arowg * NEMB + k]
                               : make_float4(0.f, 0.f, 0.f, 0.f);
        }
    };
    auto sta = [&](int buf) {
        uint32_t hw[8], lw[8];
        #pragma unroll
        for (int i = 0; i < 4; i++) {
            float4 f = af[i];
            __nv_bfloat16 hx = __float2bfloat16(f.x), hy = __float2bfloat16(f.y);
            __nv_bfloat16 hz = __float2bfloat16(f.z), hv = __float2bfloat16(f.w);
            hw[i * 2]     = bfpair(__bfloat162float(hx), __bfloat162float(hy));
            hw[i * 2 + 1] = bfpair(__bfloat162float(hz), __bfloat162float(hv));
            lw[i * 2]     = bfpair(f.x - __bfloat162float(hx), f.y - __bfloat162float(hy));
            lw[i * 2 + 1] = bfpair(f.z - __bfloat162float(hz), f.w - __bfloat162float(hv));
        }
        uint32_t doff = (uint32_t)((tid >> 2) * RSTRIDE + aq * 2);
        uint32_t base = smb + buf * BUFSZ;
        sts128(base + AHI_OFF + doff,      make_uint4(hw[0], hw[1], hw[2], hw[3]));
        sts128(base + AHI_OFF + doff + 16, make_uint4(hw[4], hw[5], hw[6], hw[7]));
        sts128(base + ALO_OFF + doff,      make_uint4(lw[0], lw[1], lw[2], lw[3]));
        sts128(base + ALO_OFF + doff + 16, make_uint4(lw[4], lw[5], lw[6], lw[7]));
    };
    auto issueB = [&](int c, int buf) {
        const uint32_t base = smb + buf * BUFSZ;
        #pragma unroll
        for (int q = 0; q < 2; q++) {
            int idx = tid + q * 512;
            int row = idx >> 3, seg = idx & 7;
            uint32_t doff = (uint32_t)(row * RSTRIDE + seg * 16);
            size_t boff = (size_t)(cbase + row) * EMBS + c * 64 + seg * 8;
            CP16(base + BHI_OFF + doff, (const char*)(g_wt_hi + boff));
            CP16(base + BLO_OFF + doff, (const char*)(g_wt_lo + boff));
        }
        CPCOMMIT();
    };

    const int wm = (wid >> 2) * 32;
    const int wn = (wid & 3) * 32;
    const uint32_t a_lane =
        (uint32_t)((wm + (lid & 7) + ((lid >> 3) & 1) * 8) * RSTRIDE + ((lid >> 4) & 1) * 16);
    const uint32_t b_lane =
        (uint32_t)((wn + (lid & 7) + ((lid >> 4) & 1) * 8) * RSTRIDE + ((lid >> 3) & 1) * 16);

    float acc[2][4][4];
    #pragma unroll
    for (int m = 0; m < 2; m++)
        #pragma unroll
        for (int j = 0; j < 4; j++)
            #pragma unroll
            for (int e = 0; e < 4; e++) acc[m][j][e] = 0.f;

    lda(0);
    issueB(0, 0);

    for (int c = 0; c < 5; c++) {
        const int buf = c & 1;
        sta(buf);                                  // A(c) -> smem buf
        if (c + 1 < 5) {
            lda(c + 1);                            // prefetch next A (overlaps mma)
            issueB(c + 1, buf ^ 1);
            CPWAIT1();                             // B(c) arrived
        } else {
            CPWAIT0();
        }
        __syncthreads();

        const uint32_t bb = smb + buf * BUFSZ;
        #pragma unroll
        for (int ks = 0; ks < 4; ks++) {
            const uint32_t ko = ks * 32;
            uint32_t ah[2][4], al[2][4], bh[2][4], bl[2][4];
            #pragma unroll
            for (int mt = 0; mt < 2; mt++) {
                ldm4(ah[mt], bb + AHI_OFF + a_lane + mt * (16 * RSTRIDE) + ko);
                ldm4(al[mt], bb + ALO_OFF + a_lane + mt * (16 * RSTRIDE) + ko);
            }
            #pragma unroll
            for (int np = 0; np < 2; np++) {
                ldm4(bh[np], bb + BHI_OFF + b_lane + np * (16 * RSTRIDE) + ko);
                ldm4(bl[np], bb + BLO_OFF + b_lane + np * (16 * RSTRIDE) + ko);
            }
            #pragma unroll
            for (int mt = 0; mt < 2; mt++)
                #pragma unroll
                for (int j = 0; j < 4; j++)
                    mma16816(acc[mt][j], ah[mt], bh[j >> 1][(j & 1) * 2], bh[j >> 1][(j & 1) * 2 + 1]);
            #pragma unroll
            for (int mt = 0; mt < 2; mt++)
                #pragma unroll
                for (int j = 0; j < 4; j++)
                    mma16816(acc[mt][j], al[mt], bh[j >> 1][(j & 1) * 2], bh[j >> 1][(j & 1) * 2 + 1]);
            #pragma unroll
            for (int mt = 0; mt < 2; mt++)
                #pragma unroll
                for (int j = 0; j < 4; j++)
                    mma16816(acc[mt][j], ah[mt], bl[j >> 1][(j & 1) * 2], bl[j >> 1][(j & 1) * 2 + 1]);
        }
        __syncthreads();
    }

    // epilogue -> g_proj (pad rows get garbage; never gathered)
    const int g  = lid >> 2;
    const int i2 = (lid & 3) * 2;
    #pragma unroll
    for (int mt = 0; mt < 2; mt++) {
        #pragma unroll
        for (int j = 0; j < 4; j++) {
            int row = rbase + wm + mt * 16 + g;
            int col = cbase + wn + j * 8 + i2;
            *(float2*)&g_proj[(size_t)row * NHID + col] =
                make_float2(acc[mt][j][0], acc[mt][j][1]);
            *(float2*)&g_proj[(size_t)(row + 8) * NHID + col] =
                make_float2(acc[mt][j][2], acc[mt][j][3]);
        }
    }
}

// =====================================================================
// Phase 2: recurrence (R2 structure). 128 CTAs x 256 threads, 2 rows/CTA.
// x comes straight from g_proj[word] (the gather), word ids staged in smem.
// =====================================================================
#define SQ 24
#define RQ 40
#define P2_SMEM (SQ * 256 * 16 + 2 * 512 * 4 + 2 * 512 * 4)

__global__ void __launch_bounds__(256, 1) rnn_kernel(
    const int* __restrict__ words,
    const float* __restrict__ Wh,
    const float* __restrict__ fcw,
    const float* __restrict__ fcb,
    float* __restrict__ out)
{
    extern __shared__ __align__(16) char smem[];
    ulonglong2* WhS = (ulonglong2*)smem;
    float*      hb  = (float*)(smem + SQ * 256 * 16);          // [2][2][256]
    int*        wsm = (int*)(smem + SQ * 256 * 16 + 2 * 512 * 4); // [2][512]

    const int j  = threadIdx.x;
    const int r0 = blockIdx.x * 2;
    const int r1 = r0 + 1;

    for (int i = j; i < SQ * 256; i += 256) {
        int q = i >> 8, c = i & 255, kr = 4 * q;
        float4 v = make_float4(Wh[kr * NHID + c],       Wh[(kr + 1) * NHID + c],
                               Wh[(kr + 2) * NHID + c], Wh[(kr + 3) * NHID + c]);
        ((float4*)smem)[i] = v;
    }
    for (int i = j; i < SEQLEN; i += 256) {
        wsm[i]          = words[r0 * SEQLEN + i];
        wsm[SEQLEN + i] = words[r1 * SEQLEN + i];
    }
    ulonglong2 whr[RQ];
    #pragma unroll
    for (int q = 0; q < RQ; q++) {
        int kr = 96 + 4 * q;
        whr[q].x = pack2(Wh[kr * NHID + j],       Wh[(kr + 1) * NHID + j]);
        whr[q].y = pack2(Wh[(kr + 2) * NHID + j], Wh[(kr + 3) * NHID + j]);
    }
    hb[j] = 0.f; hb[256 + j] = 0.f;
    __syncthreads();

    float x0 = g_proj[(size_t)wsm[0] * NHID + j];
    float x1 = g_proj[(size_t)wsm[SEQLEN] * NHID + j];

    int buf = 0;
    for (int t = 0; t < SEQLEN; t++) {
        const ulonglong2* H0 = (const ulonglong2*)(hb + buf * 512);
        const ulonglong2* H1 = H0 + 64;

        ull a0 = 0, a1 = 0;
        #pragma unroll 8
        for (int q = 0; q < SQ; q++) {
            ulonglong2 w  = WhS[q * 256 + j];
            ulonglong2 h0 = H0[q];
            ulonglong2 h1 = H1[q];
            fma2(a0, h0.x, w.x); fma2(a0, h0.y, w.y);
            fma2(a1, h1.x, w.x); fma2(a1, h1.y, w.y);
        }
        #pragma unroll
        for (int q = 0; q < RQ; q++) {
            ulonglong2 h0 = H0[SQ + q];
            ulonglong2 h1 = H1[SQ + q];
            fma2(a0, h0.x, whr[q].x); fma2(a0, h0.y, whr[q].y);
            fma2(a1, h1.x, whr[q].x); fma2(a1, h1.y, whr[q].y);
        }

        float2 s0 = unpack2(a0), s1 = unpack2(a1);
        float hn0 = sigmoidf(x0 + s0.x + s0.y);
        float hn1 = sigmoidf(x1 + s1.x + s1.y);

        if (t + 1 < SEQLEN) {
            x0 = g_proj[(size_t)wsm[t + 1] * NHID + j];
            x1 = g_proj[(size_t)wsm[SEQLEN + t + 1] * NHID + j];
        }

        int nb = buf ^ 1;
        hb[nb * 512 + j]       = hn0;
        hb[nb * 512 + 256 + j] = hn1;
        __syncthreads();
        buf = nb;
    }

    out[256 + r0 * NHID + j] = hb[buf * 512 + j];
    out[256 + r1 * NHID + j] = hb[buf * 512 + 256 + j];

    int w = j >> 5, l = j & 31;
    if (w < 2) {
        float s = 0.f;
        #pragma unroll
        for (int q = 0; q < 8; q++)
            s += hb[buf * 512 + w * 256 + l + q * 32] * fcw[l + q * 32];
        #pragma unroll
        for (int o = 16; o; o >>= 1)
            s += __shfl_xor_sync(0xffffffffu, s, o);
        if (l == 0)
            out[r0 + w] = sigmoidf(s + fcb[0]);
    }
}

// =====================================================================
extern "C" void kernel_launch(void* const* d_in, const int* in_sizes, int n_in,
                              void* d_out, int out_size)
{
    const int*   words = (const int*)  d_in[0];
    const float* emb   = (const float*)d_in[1];
    const float* Wi    = (const float*)d_in[2];
    const float* Wh    = (const float*)d_in[3];
    const float* fcw   = (const float*)d_in[4];
    const float* fcb   = (const float*)d_in[5];
    float*       out   = (float*)d_out;

    cudaFuncSetAttribute(proj_gemm, cudaFuncAttributeMaxDynamicSharedMemorySize, G8_SMEM);
    cudaFuncSetAttribute(rnn_kernel, cudaFuncAttributeMaxDynamicSharedMemorySize, P2_SMEM);

    convert_wi_kernel<<<NHID, 128>>>(Wi);
    proj_gemm<<<dim3(M_PAD / 128, NHID / 128), 512, G8_SMEM>>>(emb);
    rnn_kernel<<<BATCHN / 2, 256, P2_SMEM>>>(words, Wh, fcw, fcb, out);
}

// round 9
// speedup vs baseline: 2.0283x; 1.0158x over previous
#include <cuda_runtime.h>
#include <cuda_bf16.h>
#include <cstdint>

#define BATCHN 256
#define SEQLEN 512
#define NEMB   300
#define NHID   256
#define EMBS   320          // padded K (5 chunks of 64)
#define M_PAD  50304        // vocab rows padded to 128

typedef unsigned long long ull;

// ---------- packed f32x2 helpers (rnn path) ----------
__device__ __forceinline__ void fma2(ull &d, ull a, ull b) {
    asm("fma.rn.f32x2 %0, %1, %2, %0;" : "+l"(d) : "l"(a), "l"(b));
}
__device__ __forceinline__ ull pack2(float x, float y) {
    ull r; asm("mov.b64 %0, {%1, %2};" : "=l"(r) : "f"(x), "f"(y)); return r;
}
__device__ __forceinline__ float2 unpack2(ull v) {
    float2 r; asm("mov.b64 {%0, %1}, %2;" : "=f"(r.x), "=f"(r.y) : "l"(v)); return r;
}
__device__ __forceinline__ float sigmoidf(float z) {
    return 1.0f / (1.0f + __expf(-z));
}

// ---------- HMMA / ldmatrix / cp.async helpers ----------
__device__ __forceinline__ uint32_t smem_u32(const void* p) {
    uint32_t a;
    asm("{ .reg .u64 t; cvta.to.shared.u64 t, %1; cvt.u32.u64 %0, t; }" : "=r"(a) : "l"(p));
    return a;
}
__device__ __forceinline__ void ldm4(uint32_t* r, uint32_t addr) {
    asm volatile("ldmatrix.sync.aligned.m8n8.x4.shared.b16 {%0,%1,%2,%3}, [%4];"
                 : "=r"(r[0]), "=r"(r[1]), "=r"(r[2]), "=r"(r[3]) : "r"(addr));
}
__device__ __forceinline__ void mma16816(float* d, const uint32_t* a, uint32_t b0, uint32_t b1) {
    asm volatile(
        "mma.sync.aligned.m16n8k16.row.col.f32.bf16.bf16.f32 "
        "{%0,%1,%2,%3}, {%4,%5,%6,%7}, {%8,%9}, {%0,%1,%2,%3};"
        : "+f"(d[0]), "+f"(d[1]), "+f"(d[2]), "+f"(d[3])
        : "r"(a[0]), "r"(a[1]), "r"(a[2]), "r"(a[3]), "r"(b0), "r"(b1));
}
__device__ __forceinline__ uint32_t bfpair(float a, float b) {
    __nv_bfloat162 t = __floats2bfloat162_rn(a, b);
    return *(uint32_t*)&t;
}
__device__ __forceinline__ void sts128(uint32_t addr, uint4 v) {
    asm volatile("st.shared.v4.b32 [%0], {%1,%2,%3,%4};"
                 :: "r"(addr), "r"(v.x), "r"(v.y), "r"(v.z), "r"(v.w) : "memory");
}
#define CP16(dst, src) asm volatile("cp.async.cg.shared.global [%0], [%1], 16;" :: "r"(dst), "l"(src) : "memory")
#define CPCOMMIT()     asm volatile("cp.async.commit_group;" ::: "memory")
#define CPWAIT1()      asm volatile("cp.async.wait_group 1;" ::: "memory")
#define CPWAIT0()      asm volatile("cp.async.wait_group 0;" ::: "memory")

// ---------- device scratch ----------
__device__ float g_proj[(size_t)M_PAD * NHID];                // 51.5 MB: proj = emb @ Wi
__device__ __nv_bfloat16 g_wt_hi[256 * EMBS];                 // Wi^T hi  [n][k]
__device__ __nv_bfloat16 g_wt_lo[256 * EMBS];                 // Wi^T lo  [n][k]

// =====================================================================
// Wi^T split-convert: fp32 -> (hi, lo) bf16, K zero-padded to 320.
// =====================================================================
__global__ __launch_bounds__(128) void convert_wi_kernel(const float* __restrict__ Wi)
{
    const int n = blockIdx.x, tid = threadIdx.x;
    for (int k = tid; k < EMBS; k += 128) {
        float v = (k < NEMB) ? Wi[k * NHID + n] : 0.f;
        __nv_bfloat16 h = __float2bfloat16(v);
        g_wt_hi[n * EMBS + k] = h;
        g_wt_lo[n * EMBS + k] = __float2bfloat16(v - __bfloat162float(h));
    }
}

// =====================================================================
// proj = emb @ Wi via 3-GEMM bf16 split on HMMA. CTA 128x128, 512 thr.
// A (emb) converted fp32->hi/lo ON THE FLY; B (Wi^T hi/lo) via cp.async
// double-buffer. K = 5 chunks of 64. 144B row stride, conflict-free ldmatrix.
// =====================================================================
#define RSTRIDE 144
#define AHI_OFF 0
#define ALO_OFF 18432
#define BHI_OFF 36864
#define BLO_OFF 55296
#define BUFSZ   73728
#define G8_SMEM (2 * BUFSZ + 64)

__global__ void __launch_bounds__(512, 1) proj_gemm(const float* __restrict__ emb)
{
    extern __shared__ __align__(16) char dsm[];
    const uint32_t smb = smem_u32(dsm);

    const int tid = threadIdx.x, wid = tid >> 5, lid = tid & 31;
    const int rbase = blockIdx.x * 128;
    const int cbase = blockIdx.y * 128;

    const int arow  = rbase + (tid >> 2);
    const int arowg = (arow < 50257) ? arow : 50256;
    const int aq    = (tid & 3) * 16;
    float4 af[4];

    auto lda = [&](int c) {
        #pragma unroll
        for (int i = 0; i < 4; i++) {
            int k = c * 64 + aq + i * 4;
            af[i] = (k < NEMB) ? *(const float4*)&emb[(size_t)arowg * NEMB + k]
                               : make_float4(0.f, 0.f, 0.f, 0.f);
        }
    };
    auto sta = [&](int buf) {
        uint32_t hw[8], lw[8];
        #pragma unroll
        for (int i = 0; i < 4; i++) {
            float4 f = af[i];
            __nv_bfloat16 hx = __float2bfloat16(f.x), hy = __float2bfloat16(f.y);
            __nv_bfloat16 hz = __float2bfloat16(f.z), hv = __float2bfloat16(f.w);
            hw[i * 2]     = bfpair(__bfloat162float(hx), __bfloat162float(hy));
            hw[i * 2 + 1] = bfpair(__bfloat162float(hz), __bfloat162float(hv));
            lw[i * 2]     = bfpair(f.x - __bfloat162float(hx), f.y - __bfloat162float(hy));
            lw[i * 2 + 1] = bfpair(f.z - __bfloat162float(hz), f.w - __bfloat162float(hv));
        }
        uint32_t doff = (uint32_t)((tid >> 2) * RSTRIDE + aq * 2);
        uint32_t base = smb + buf * BUFSZ;
        sts128(base + AHI_OFF + doff,      make_uint4(hw[0], hw[1], hw[2], hw[3]));
        sts128(base + AHI_OFF + doff + 16, make_uint4(hw[4], hw[5], hw[6], hw[7]));
        sts128(base + ALO_OFF + doff,      make_uint4(lw[0], lw[1], lw[2], lw[3]));
        sts128(base + ALO_OFF + doff + 16, make_uint4(lw[4], lw[5], lw[6], lw[7]));
    };
    auto issueB = [&](int c, int buf) {
        const uint32_t base = smb + buf * BUFSZ;
        #pragma unroll
        for (int q = 0; q < 2; q++) {
            int idx = tid + q * 512;
            int row = idx >> 3, seg = idx & 7;
            uint32_t doff = (uint32_t)(row * RSTRIDE + seg * 16);
            size_t boff = (size_t)(cbase + row) * EMBS + c * 64 + seg * 8;
            CP16(base + BHI_OFF + doff, (const char*)(g_wt_hi + boff));
            CP16(base + BLO_OFF + doff, (const char*)(g_wt_lo + boff));
        }
        CPCOMMIT();
    };

    const int wm = (wid >> 2) * 32;
    const int wn = (wid & 3) * 32;
    const uint32_t a_lane =
        (uint32_t)((wm + (lid & 7) + ((lid >> 3) & 1) * 8) * RSTRIDE + ((lid >> 4) & 1) * 16);
    const uint32_t b_lane =
        (uint32_t)((wn + (lid & 7) + ((lid >> 4) & 1) * 8) * RSTRIDE + ((lid >> 3) & 1) * 16);

    float acc[2][4][4];
    #pragma unroll
    for (int m = 0; m < 2; m++)
        #pragma unroll
        for (int j = 0; j < 4; j++)
            #pragma unroll
            for (int e = 0; e < 4; e++) acc[m][j][e] = 0.f;

    lda(0);
    issueB(0, 0);

    for (int c = 0; c < 5; c++) {
        const int buf = c & 1;
        sta(buf);
        if (c + 1 < 5) {
            lda(c + 1);
            issueB(c + 1, buf ^ 1);
            CPWAIT1();
        } else {
            CPWAIT0();
        }
        __syncthreads();

        const uint32_t bb = smb + buf * BUFSZ;
        #pragma unroll
        for (int ks = 0; ks < 4; ks++) {
            const uint32_t ko = ks * 32;
            uint32_t ah[2][4], al[2][4], bh[2][4], bl[2][4];
            #pragma unroll
            for (int mt = 0; mt < 2; mt++) {
                ldm4(ah[mt], bb + AHI_OFF + a_lane + mt * (16 * RSTRIDE) + ko);
                ldm4(al[mt], bb + ALO_OFF + a_lane + mt * (16 * RSTRIDE) + ko);
            }
            #pragma unroll
            for (int np = 0; np < 2; np++) {
                ldm4(bh[np], bb + BHI_OFF + b_lane + np * (16 * RSTRIDE) + ko);
                ldm4(bl[np], bb + BLO_OFF + b_lane + np * (16 * RSTRIDE) + ko);
            }
            #pragma unroll
            for (int mt = 0; mt < 2; mt++)
                #pragma unroll
                for (int j = 0; j < 4; j++)
                    mma16816(acc[mt][j], ah[mt], bh[j >> 1][(j & 1) * 2], bh[j >> 1][(j & 1) * 2 + 1]);
            #pragma unroll
            for (int mt = 0; mt < 2; mt++)
                #pragma unroll
                for (int j = 0; j < 4; j++)
                    mma16816(acc[mt][j], al[mt], bh[j >> 1][(j & 1) * 2], bh[j >> 1][(j & 1) * 2 + 1]);
            #pragma unroll
            for (int mt = 0; mt < 2; mt++)
                #pragma unroll
                for (int j = 0; j < 4; j++)
                    mma16816(acc[mt][j], ah[mt], bl[j >> 1][(j & 1) * 2], bl[j >> 1][(j & 1) * 2 + 1]);
        }
        __syncthreads();
    }

    const int g  = lid >> 2;
    const int i2 = (lid & 3) * 2;
    #pragma unroll
    for (int mt = 0; mt < 2; mt++) {
        #pragma unroll
        for (int j = 0; j < 4; j++) {
            int row = rbase + wm + mt * 16 + g;
            int col = cbase + wn + j * 8 + i2;
            *(float2*)&g_proj[(size_t)row * NHID + col] =
                make_float2(acc[mt][j][0], acc[mt][j][1]);
            *(float2*)&g_proj[(size_t)(row + 8) * NHID + col] =
                make_float2(acc[mt][j][2], acc[mt][j][3]);
        }
    }
}

// =====================================================================
// Phase 2: recurrence. 128 CTAs x 256 threads, 2 rows/CTA, col j/thread.
// Wh rows 0..87 in smem (SQ=22), rows 88..255 in regs (RQ=42).
// 4 independent accumulator chains (2 per row) for ILP.
// x gathered straight from g_proj[word]; word ids staged in smem.
// =====================================================================
#define SQ 22
#define RQ 42
#define P2_SMEM (SQ * 256 * 16 + 2 * 512 * 4 + 2 * 512 * 4)

__global__ void __launch_bounds__(256, 1) rnn_kernel(
    const int* __restrict__ words,
    const float* __restrict__ Wh,
    const float* __restrict__ fcw,
    const float* __restrict__ fcb,
    float* __restrict__ out)
{
    extern __shared__ __align__(16) char smem[];
    ulonglong2* WhS = (ulonglong2*)smem;
    float*      hb  = (float*)(smem + SQ * 256 * 16);             // [2][2][256]
    int*        wsm = (int*)(smem + SQ * 256 * 16 + 2 * 512 * 4); // [2][512]

    const int j  = threadIdx.x;
    const int r0 = blockIdx.x * 2;
    const int r1 = r0 + 1;

    for (int i = j; i < SQ * 256; i += 256) {
        int q = i >> 8, c = i & 255, kr = 4 * q;
        float4 v = make_float4(Wh[kr * NHID + c],       Wh[(kr + 1) * NHID + c],
                               Wh[(kr + 2) * NHID + c], Wh[(kr + 3) * NHID + c]);
        ((float4*)smem)[i] = v;
    }
    for (int i = j; i < SEQLEN; i += 256) {
        wsm[i]          = words[r0 * SEQLEN + i];
        wsm[SEQLEN + i] = words[r1 * SEQLEN + i];
    }
    ulonglong2 whr[RQ];
    #pragma unroll
    for (int q = 0; q < RQ; q++) {
        int kr = SQ * 4 + 4 * q;
        whr[q].x = pack2(Wh[kr * NHID + j],       Wh[(kr + 1) * NHID + j]);
        whr[q].y = pack2(Wh[(kr + 2) * NHID + j], Wh[(kr + 3) * NHID + j]);
    }
    hb[j] = 0.f; hb[256 + j] = 0.f;
    __syncthreads();

    float x0 = g_proj[(size_t)wsm[0] * NHID + j];
    float x1 = g_proj[(size_t)wsm[SEQLEN] * NHID + j];

    int buf = 0;
    for (int t = 0; t < SEQLEN; t++) {
        const ulonglong2* H0 = (const ulonglong2*)(hb + buf * 512);
        const ulonglong2* H1 = H0 + 64;

        // 4 independent chains: (row0,.x) (row0,.y) (row1,.x) (row1,.y)
        ull a0x = 0, a0y = 0, a1x = 0, a1y = 0;
        #pragma unroll 11
        for (int q = 0; q < SQ; q++) {
            ulonglong2 w  = WhS[q * 256 + j];
            ulonglong2 h0 = H0[q];
            ulonglong2 h1 = H1[q];
            fma2(a0x, h0.x, w.x); fma2(a0y, h0.y, w.y);
            fma2(a1x, h1.x, w.x); fma2(a1y, h1.y, w.y);
        }
        #pragma unroll
        for (int q = 0; q < RQ; q++) {
            ulonglong2 h0 = H0[SQ + q];
            ulonglong2 h1 = H1[SQ + q];
            fma2(a0x, h0.x, whr[q].x); fma2(a0y, h0.y, whr[q].y);
            fma2(a1x, h1.x, whr[q].x); fma2(a1y, h1.y, whr[q].y);
        }

        float2 s0a = unpack2(a0x), s0b = unpack2(a0y);
        float2 s1a = unpack2(a1x), s1b = unpack2(a1y);
        float hn0 = sigmoidf(x0 + (s0a.x + s0a.y) + (s0b.x + s0b.y));
        float hn1 = sigmoidf(x1 + (s1a.x + s1a.y) + (s1b.x + s1b.y));

        if (t + 1 < SEQLEN) {
            x0 = g_proj[(size_t)wsm[t + 1] * NHID + j];
            x1 = g_proj[(size_t)wsm[SEQLEN + t + 1] * NHID + j];
        }

        int nb = buf ^ 1;
        hb[nb * 512 + j]       = hn0;
        hb[nb * 512 + 256 + j] = hn1;
        __syncthreads();
        buf = nb;
    }

    out[256 + r0 * NHID + j] = hb[buf * 512 + j];
    out[256 + r1 * NHID + j] = hb[buf * 512 + 256 + j];

    int w = j >> 5, l = j & 31;
    if (w < 2) {
        float s = 0.f;
        #pragma unroll
        for (int q = 0; q < 8; q++)
            s += hb[buf * 512 + w * 256 + l + q * 32] * fcw[l + q * 32];
        #pragma unroll
        for (int o = 16; o; o >>= 1)
            s += __shfl_xor_sync(0xffffffffu, s, o);
        if (l == 0)
            out[r0 + w] = sigmoidf(s + fcb[0]);
    }
}

// =====================================================================
extern "C" void kernel_launch(void* const* d_in, const int* in_sizes, int n_in,
                              void* d_out, int out_size)
{
    const int*   words = (const int*)  d_in[0];
    const float* emb   = (const float*)d_in[1];
    const float* Wi    = (const float*)d_in[2];
    const float* Wh    = (const float*)d_in[3];
    const float* fcw   = (const float*)d_in[4];
    const float* fcb   = (const float*)d_in[5];
    float*       out   = (float*)d_out;

    cudaFuncSetAttribute(proj_gemm, cudaFuncAttributeMaxDynamicSharedMemorySize, G8_SMEM);
    cudaFuncSetAttribute(rnn_kernel, cudaFuncAttributeMaxDynamicSharedMemorySize, P2_SMEM);

    convert_wi_kernel<<<NHID, 128>>>(Wi);
    proj_gemm<<<dim3(M_PAD / 128, NHID / 128), 512, G8_SMEM>>>(emb);
    rnn_kernel<<<BATCHN / 2, 256, P2_SMEM>>>(words, Wh, fcw, fcb, out);
}

// round 10
// speedup vs baseline: 2.4025x; 1.1845x over previous
#include <cuda_runtime.h>
#include <cuda_bf16.h>
#include <cstdint>

#define BATCHN 256
#define SEQLEN 512
#define NEMB   300
#define NHID   256
#define EMBS   320          // padded K (5 chunks of 64)
#define M_PAD  50304        // vocab rows padded to 128

typedef unsigned long long ull;

// ---------- packed f32x2 helpers (rnn path) ----------
__device__ __forceinline__ void fma2(ull &d, ull a, ull b) {
    asm("fma.rn.f32x2 %0, %1, %2, %0;" : "+l"(d) : "l"(a), "l"(b));
}
__device__ __forceinline__ ull pack2(float x, float y) {
    ull r; asm("mov.b64 %0, {%1, %2};" : "=l"(r) : "f"(x), "f"(y)); return r;
}
__device__ __forceinline__ float2 unpack2(ull v) {
    float2 r; asm("mov.b64 {%0, %1}, %2;" : "=f"(r.x), "=f"(r.y) : "l"(v)); return r;
}
__device__ __forceinline__ float sigmoidf(float z) {
    return 1.0f / (1.0f + __expf(-z));
}

// ---------- HMMA / ldmatrix / cp.async helpers ----------
__device__ __forceinline__ uint32_t smem_u32(const void* p) {
    uint32_t a;
    asm("{ .reg .u64 t; cvta.to.shared.u64 t, %1; cvt.u32.u64 %0, t; }" : "=r"(a) : "l"(p));
    return a;
}
__device__ __forceinline__ void ldm4(uint32_t* r, uint32_t addr) {
    asm volatile("ldmatrix.sync.aligned.m8n8.x4.shared.b16 {%0,%1,%2,%3}, [%4];"
                 : "=r"(r[0]), "=r"(r[1]), "=r"(r[2]), "=r"(r[3]) : "r"(addr));
}
__device__ __forceinline__ void mma16816(float* d, const uint32_t* a, uint32_t b0, uint32_t b1) {
    asm volatile(
        "mma.sync.aligned.m16n8k16.row.col.f32.bf16.bf16.f32 "
        "{%0,%1,%2,%3}, {%4,%5,%6,%7}, {%8,%9}, {%0,%1,%2,%3};"
        : "+f"(d[0]), "+f"(d[1]), "+f"(d[2]), "+f"(d[3])
        : "r"(a[0]), "r"(a[1]), "r"(a[2]), "r"(a[3]), "r"(b0), "r"(b1));
}
__device__ __forceinline__ uint32_t bfpair(float a, float b) {
    __nv_bfloat162 t = __floats2bfloat162_rn(a, b);
    return *(uint32_t*)&t;
}
__device__ __forceinline__ void sts128(uint32_t addr, uint4 v) {
    asm volatile("st.shared.v4.b32 [%0], {%1,%2,%3,%4};"
                 :: "r"(addr), "r"(v.x), "r"(v.y), "r"(v.z), "r"(v.w) : "memory");
}
#define CP16(dst, src) asm volatile("cp.async.cg.shared.global [%0], [%1], 16;" :: "r"(dst), "l"(src) : "memory")
#define CPCOMMIT()     asm volatile("cp.async.commit_group;" ::: "memory")
#define CPWAIT1()      asm volatile("cp.async.wait_group 1;" ::: "memory")
#define CPWAIT0()      asm volatile("cp.async.wait_group 0;" ::: "memory")

// ---------- device scratch ----------
__device__ float g_proj[(size_t)M_PAD * NHID];                // 51.5 MB: proj = emb @ Wi
__device__ __nv_bfloat16 g_wt_hi[256 * EMBS];                 // Wi^T hi  [n][k]
__device__ __nv_bfloat16 g_wt_lo[256 * EMBS];                 // Wi^T lo  [n][k]

// =====================================================================
// Wi^T split-convert: fp32 -> (hi, lo) bf16, K zero-padded to 320.
// =====================================================================
__global__ __launch_bounds__(128) void convert_wi_kernel(const float* __restrict__ Wi)
{
    const int n = blockIdx.x, tid = threadIdx.x;
    for (int k = tid; k < EMBS; k += 128) {
        float v = (k < NEMB) ? Wi[k * NHID + n] : 0.f;
        __nv_bfloat16 h = __float2bfloat16(v);
        g_wt_hi[n * EMBS + k] = h;
        g_wt_lo[n * EMBS + k] = __float2bfloat16(v - __bfloat162float(h));
    }
}

// =====================================================================
// proj = emb @ Wi via 3-GEMM bf16 split on HMMA. CTA 128x128, 512 thr.
// (unchanged from R8)
// =====================================================================
#define RSTRIDE 144
#define AHI_OFF 0
#define ALO_OFF 18432
#define BHI_OFF 36864
#define BLO_OFF 55296
#define BUFSZ   73728
#define G8_SMEM (2 * BUFSZ + 64)

__global__ void __launch_bounds__(512, 1) proj_gemm(const float* __restrict__ emb)
{
    extern __shared__ __align__(16) char dsm[];
    const uint32_t smb = smem_u32(dsm);

    const int tid = threadIdx.x, wid = tid >> 5, lid = tid & 31;
    const int rbase = blockIdx.x * 128;
    const int cbase = blockIdx.y * 128;

    const int arow  = rbase + (tid >> 2);
    const int arowg = (arow < 50257) ? arow : 50256;
    const int aq    = (tid & 3) * 16;
    float4 af[4];

    auto lda = [&](int c) {
        #pragma unroll
        for (int i = 0; i < 4; i++) {
            int k = c * 64 + aq + i * 4;
            af[i] = (k < NEMB) ? *(const float4*)&emb[(size_t)arowg * NEMB + k]
                               : make_float4(0.f, 0.f, 0.f, 0.f);
        }
    };
    auto sta = [&](int buf) {
        uint32_t hw[8], lw[8];
        #pragma unroll
        for (int i = 0; i < 4; i++) {
            float4 f = af[i];
            __nv_bfloat16 hx = __float2bfloat16(f.x), hy = __float2bfloat16(f.y);
            __nv_bfloat16 hz = __float2bfloat16(f.z), hv = __float2bfloat16(f.w);
            hw[i * 2]     = bfpair(__bfloat162float(hx), __bfloat162float(hy));
            hw[i * 2 + 1] = bfpair(__bfloat162float(hz), __bfloat162float(hv));
            lw[i * 2]     = bfpair(f.x - __bfloat162float(hx), f.y - __bfloat162float(hy));
            lw[i * 2 + 1] = bfpair(f.z - __bfloat162float(hz), f.w - __bfloat162float(hv));
        }
        uint32_t doff = (uint32_t)((tid >> 2) * RSTRIDE + aq * 2);
        uint32_t base = smb + buf * BUFSZ;
        sts128(base + AHI_OFF + doff,      make_uint4(hw[0], hw[1], hw[2], hw[3]));
        sts128(base + AHI_OFF + doff + 16, make_uint4(hw[4], hw[5], hw[6], hw[7]));
        sts128(base + ALO_OFF + doff,      make_uint4(lw[0], lw[1], lw[2], lw[3]));
        sts128(base + ALO_OFF + doff + 16, make_uint4(lw[4], lw[5], lw[6], lw[7]));
    };
    auto issueB = [&](int c, int buf) {
        const uint32_t base = smb + buf * BUFSZ;
        #pragma unroll
        for (int q = 0; q < 2; q++) {
            int idx = tid + q * 512;
            int row = idx >> 3, seg = idx & 7;
            uint32_t doff = (uint32_t)(row * RSTRIDE + seg * 16);
            size_t boff = (size_t)(cbase + row) * EMBS + c * 64 + seg * 8;
            CP16(base + BHI_OFF + doff, (const char*)(g_wt_hi + boff));
            CP16(base + BLO_OFF + doff, (const char*)(g_wt_lo + boff));
        }
        CPCOMMIT();
    };

    const int wm = (wid >> 2) * 32;
    const int wn = (wid & 3) * 32;
    const uint32_t a_lane =
        (uint32_t)((wm + (lid & 7) + ((lid >> 3) & 1) * 8) * RSTRIDE + ((lid >> 4) & 1) * 16);
    const uint32_t b_lane =
        (uint32_t)((wn + (lid & 7) + ((lid >> 4) & 1) * 8) * RSTRIDE + ((lid >> 3) & 1) * 16);

    float acc[2][4][4];
    #pragma unroll
    for (int m = 0; m < 2; m++)
        #pragma unroll
        for (int j = 0; j < 4; j++)
            #pragma unroll
            for (int e = 0; e < 4; e++) acc[m][j][e] = 0.f;

    lda(0);
    issueB(0, 0);

    for (int c = 0; c < 5; c++) {
        const int buf = c & 1;
        sta(buf);
        if (c + 1 < 5) {
            lda(c + 1);
            issueB(c + 1, buf ^ 1);
            CPWAIT1();
        } else {
            CPWAIT0();
        }
        __syncthreads();

        const uint32_t bb = smb + buf * BUFSZ;
        #pragma unroll
        for (int ks = 0; ks < 4; ks++) {
            const uint32_t ko = ks * 32;
            uint32_t ah[2][4], al[2][4], bh[2][4], bl[2][4];
            #pragma unroll
            for (int mt = 0; mt < 2; mt++) {
                ldm4(ah[mt], bb + AHI_OFF + a_lane + mt * (16 * RSTRIDE) + ko);
                ldm4(al[mt], bb + ALO_OFF + a_lane + mt * (16 * RSTRIDE) + ko);
            }
            #pragma unroll
            for (int np = 0; np < 2; np++) {
                ldm4(bh[np], bb + BHI_OFF + b_lane + np * (16 * RSTRIDE) + ko);
                ldm4(bl[np], bb + BLO_OFF + b_lane + np * (16 * RSTRIDE) + ko);
            }
            #pragma unroll
            for (int mt = 0; mt < 2; mt++)
                #pragma unroll
                for (int j = 0; j < 4; j++)
                    mma16816(acc[mt][j], ah[mt], bh[j >> 1][(j & 1) * 2], bh[j >> 1][(j & 1) * 2 + 1]);
            #pragma unroll
            for (int mt = 0; mt < 2; mt++)
                #pragma unroll
                for (int j = 0; j < 4; j++)
                    mma16816(acc[mt][j], al[mt], bh[j >> 1][(j & 1) * 2], bh[j >> 1][(j & 1) * 2 + 1]);
            #pragma unroll
            for (int mt = 0; mt < 2; mt++)
                #pragma unroll
                for (int j = 0; j < 4; j++)
                    mma16816(acc[mt][j], ah[mt], bl[j >> 1][(j & 1) * 2], bl[j >> 1][(j & 1) * 2 + 1]);
        }
        __syncthreads();
    }

    const int g  = lid >> 2;
    const int i2 = (lid & 3) * 2;
    #pragma unroll
    for (int mt = 0; mt < 2; mt++) {
        #pragma unroll
        for (int j = 0; j < 4; j++) {
            int row = rbase + wm + mt * 16 + g;
            int col = cbase + wn + j * 8 + i2;
            *(float2*)&g_proj[(size_t)row * NHID + col] =
                make_float2(acc[mt][j][0], acc[mt][j][1]);
            *(float2*)&g_proj[(size_t)(row + 8) * NHID + col] =
                make_float2(acc[mt][j][2], acc[mt][j][3]);
        }
    }
}

// =====================================================================
// Phase 2: K-SPLIT recurrence. 128 CTAs x 256 threads, 2 rows/CTA.
// Warps 0-3 (half 0): k in [0,128); warps 4-7 (half 1): k in [128,256).
// Thread (half, jj) covers columns jj and jj+128 over its k-half, both rows.
// Per column-half: SQr=10 q-groups from smem, RQr=22 from registers (176 regs).
// Partial sums exchanged via smem; half h finalizes row h. 2 barriers/step.
// Crossbar demand ~1230 wf/step (was 1728).
// =====================================================================
#define SQr 10
#define RQr 22
#define WH_BYTES (2 * SQr * 256 * 16)          // 80 KB
#define HB_OFF   WH_BYTES
#define PART_OFF (HB_OFF + 2 * 512 * 4)
#define WSM_OFF  (PART_OFF + 4 * 256 * 4)
#define P2_SMEM  (WSM_OFF + 2 * 512 * 4)

__global__ void __launch_bounds__(256, 1) rnn_kernel(
    const int* __restrict__ words,
    const float* __restrict__ Wh,
    const float* __restrict__ fcw,
    const float* __restrict__ fcb,
    float* __restrict__ out)
{
    extern __shared__ __align__(16) char smem[];
    ulonglong2* WhS  = (ulonglong2*)smem;
    float*      hb   = (float*)(smem + HB_OFF);    // [2][2][256] double-buffered h
    float*      part = (float*)(smem + PART_OFF);  // [half][row][256]
    int*        wsm  = (int*)(smem + WSM_OFF);     // [2][512]

    const int tid  = threadIdx.x;
    const int half = tid >> 7;           // k-half this thread sums
    const int jj   = tid & 127;
    const int c0   = jj, c1 = jj + 128;  // owned columns
    const int r0   = blockIdx.x * 2;
    const int qb   = 32 * half;          // global k4-group base for this half

    // Wh smem: first SQr q-groups of each half, packed float4-over-k
    for (int i = tid; i < 2 * SQr * 256; i += 256) {
        int hf = i / (SQr * 256);
        int rem = i - hf * (SQr * 256);
        int q = rem >> 8, c = rem & 255;
        int kr = hf * 128 + 4 * q;
        float4 v = make_float4(Wh[kr * NHID + c],       Wh[(kr + 1) * NHID + c],
                               Wh[(kr + 2) * NHID + c], Wh[(kr + 3) * NHID + c]);
        ((float4*)smem)[i] = v;
    }
    for (int i = tid; i < SEQLEN; i += 256) {
        wsm[i]          = words[r0 * SEQLEN + i];
        wsm[SEQLEN + i] = words[(r0 + 1) * SEQLEN + i];
    }
    // Wh registers: remaining RQr q-groups of this half, cols c0 and c1
    ulonglong2 whr0[RQr], whr1[RQr];
    #pragma unroll
    for (int q = 0; q < RQr; q++) {
        int kr = half * 128 + (SQr + q) * 4;
        whr0[q].x = pack2(Wh[kr * NHID + c0],       Wh[(kr + 1) * NHID + c0]);
        whr0[q].y = pack2(Wh[(kr + 2) * NHID + c0], Wh[(kr + 3) * NHID + c0]);
        whr1[q].x = pack2(Wh[kr * NHID + c1],       Wh[(kr + 1) * NHID + c1]);
        whr1[q].y = pack2(Wh[(kr + 2) * NHID + c1], Wh[(kr + 3) * NHID + c1]);
    }
    hb[tid] = 0.f; hb[256 + tid] = 0.f;   // buffer 0, both rows
    __syncthreads();

    // x prefetch for the row this thread finalizes (row == half), cols c0/c1
    float xa = g_proj[(size_t)wsm[half * SEQLEN] * NHID + c0];
    float xb = g_proj[(size_t)wsm[half * SEQLEN] * NHID + c1];

    int buf = 0;
    for (int t = 0; t < SEQLEN; t++) {
        const ulonglong2* H0 = (const ulonglong2*)(hb + buf * 512);
        const ulonglong2* H1 = H0 + 64;

        ull a00 = 0, a01 = 0, a10 = 0, a11 = 0;   // [row][col]
        #pragma unroll
        for (int q = 0; q < SQr; q++) {
            ulonglong2 w0 = WhS[(half * SQr + q) * 256 + c0];
            ulonglong2 w1 = WhS[(half * SQr + q) * 256 + c1];
            ulonglong2 h0 = H0[qb + q];
            ulonglong2 h1 = H1[qb + q];
            fma2(a00, h0.x, w0.x); fma2(a00, h0.y, w0.y);
            fma2(a01, h0.x, w1.x); fma2(a01, h0.y, w1.y);
            fma2(a10, h1.x, w0.x); fma2(a10, h1.y, w0.y);
            fma2(a11, h1.x, w1.x); fma2(a11, h1.y, w1.y);
        }
        #pragma unroll
        for (int q = 0; q < RQr; q++) {
            ulonglong2 h0 = H0[qb + SQr + q];
            ulonglong2 h1 = H1[qb + SQr + q];
            fma2(a00, h0.x, whr0[q].x); fma2(a00, h0.y, whr0[q].y);
            fma2(a01, h0.x, whr1[q].x); fma2(a01, h0.y, whr1[q].y);
            fma2(a10, h1.x, whr0[q].x); fma2(a10, h1.y, whr0[q].y);
            fma2(a11, h1.x, whr1[q].x); fma2(a11, h1.y, whr1[q].y);
        }

        float2 s;
        s = unpack2(a00); float p00 = s.x + s.y;
        s = unpack2(a01); float p01 = s.x + s.y;
        s = unpack2(a10); float p10 = s.x + s.y;
        s = unpack2(a11); float p11 = s.x + s.y;

        part[(half * 2 + 0) * 256 + c0] = p00;
        part[(half * 2 + 0) * 256 + c1] = p01;
        part[(half * 2 + 1) * 256 + c0] = p10;
        part[(half * 2 + 1) * 256 + c1] = p11;
        __syncthreads();

        // finalize row == half: own partial + other half's partial
        const int oh = half ^ 1;
        float o0 = part[(oh * 2 + half) * 256 + c0];
        float o1 = part[(oh * 2 + half) * 256 + c1];
        float own0 = half ? p10 : p00;
        float own1 = half ? p11 : p01;
        float hna = sigmoidf(xa + own0 + o0);
        float hnb = sigmoidf(xb + own1 + o1);

        if (t + 1 < SEQLEN) {
            size_t w = (size_t)wsm[half * SEQLEN + t + 1] * NHID;
            xa = g_proj[w + c0];
            xb = g_proj[w + c1];
        }

        int nb = buf ^ 1;
        hb[nb * 512 + half * 256 + c0] = hna;
        hb[nb * 512 + half * 256 + c1] = hnb;
        __syncthreads();
        buf = nb;
    }

    // outputs
    out[256 + r0 * NHID + tid]       = hb[buf * 512 + tid];
    out[256 + (r0 + 1) * NHID + tid] = hb[buf * 512 + 256 + tid];

    int w = tid >> 5, l = tid & 31;
    if (w < 2) {
        float s = 0.f;
        #pragma unroll
        for (int q = 0; q < 8; q++)
            s += hb[buf * 512 + w * 256 + l + q * 32] * fcw[l + q * 32];
        #pragma unroll
        for (int o = 16; o; o >>= 1)
            s += __shfl_xor_sync(0xffffffffu, s, o);
        if (l == 0)
            out[r0 + w] = sigmoidf(s + fcb[0]);
    }
}

// =====================================================================
extern "C" void kernel_launch(void* const* d_in, const int* in_sizes, int n_in,
                              void* d_out, int out_size)
{
    const int*   words = (const int*)  d_in[0];
    const float* emb   = (const float*)d_in[1];
    const float* Wi    = (const float*)d_in[2];
    const float* Wh    = (const float*)d_in[3];
    const float* fcw   = (const float*)d_in[4];
    const float* fcb   = (const float*)d_in[5];
    float*       out   = (float*)d_out;

    cudaFuncSetAttribute(proj_gemm, cudaFuncAttributeMaxDynamicSharedMemorySize, G8_SMEM);
    cudaFuncSetAttribute(rnn_kernel, cudaFuncAttributeMaxDynamicSharedMemorySize, P2_SMEM);

    convert_wi_kernel<<<NHID, 128>>>(Wi);
    proj_gemm<<<dim3(M_PAD / 128, NHID / 128), 512, G8_SMEM>>>(emb);
    rnn_kernel<<<BATCHN / 2, 256, P2_SMEM>>>(words, Wh, fcw, fcb, out);
}

// round 11
// speedup vs baseline: 2.5470x; 1.0601x over previous
#include <cuda_runtime.h>
#include <cuda_bf16.h>
#include <cstdint>

#define BATCHN 256
#define SEQLEN 512
#define NEMB   300
#define NHID   256
#define EMBS   320          // padded K (5 chunks of 64)
#define M_PAD  50304        // vocab rows padded to 128

typedef unsigned long long ull;

// ---------- packed f32x2 helpers (rnn path) ----------
__device__ __forceinline__ void fma2(ull &d, ull a, ull b) {
    asm("fma.rn.f32x2 %0, %1, %2, %0;" : "+l"(d) : "l"(a), "l"(b));
}
__device__ __forceinline__ ull pack2(float x, float y) {
    ull r; asm("mov.b64 %0, {%1, %2};" : "=l"(r) : "f"(x), "f"(y)); return r;
}
__device__ __forceinline__ float2 unpack2(ull v) {
    float2 r; asm("mov.b64 {%0, %1}, %2;" : "=f"(r.x), "=f"(r.y) : "l"(v)); return r;
}
__device__ __forceinline__ float sigmoidf(float z) {
    return 1.0f / (1.0f + __expf(-z));
}

// ---------- HMMA / ldmatrix / cp.async helpers ----------
__device__ __forceinline__ uint32_t smem_u32(const void* p) {
    uint32_t a;
    asm("{ .reg .u64 t; cvta.to.shared.u64 t, %1; cvt.u32.u64 %0, t; }" : "=r"(a) : "l"(p));
    return a;
}
__device__ __forceinline__ void ldm4(uint32_t* r, uint32_t addr) {
    asm volatile("ldmatrix.sync.aligned.m8n8.x4.shared.b16 {%0,%1,%2,%3}, [%4];"
                 : "=r"(r[0]), "=r"(r[1]), "=r"(r[2]), "=r"(r[3]) : "r"(addr));
}
__device__ __forceinline__ void mma16816(float* d, const uint32_t* a, uint32_t b0, uint32_t b1) {
    asm volatile(
        "mma.sync.aligned.m16n8k16.row.col.f32.bf16.bf16.f32 "
        "{%0,%1,%2,%3}, {%4,%5,%6,%7}, {%8,%9}, {%0,%1,%2,%3};"
        : "+f"(d[0]), "+f"(d[1]), "+f"(d[2]), "+f"(d[3])
        : "r"(a[0]), "r"(a[1]), "r"(a[2]), "r"(a[3]), "r"(b0), "r"(b1));
}
__device__ __forceinline__ uint32_t bfpair(float a, float b) {
    __nv_bfloat162 t = __floats2bfloat162_rn(a, b);
    return *(uint32_t*)&t;
}
__device__ __forceinline__ void sts128(uint32_t addr, uint4 v) {
    asm volatile("st.shared.v4.b32 [%0], {%1,%2,%3,%4};"
                 :: "r"(addr), "r"(v.x), "r"(v.y), "r"(v.z), "r"(v.w) : "memory");
}
#define CP16(dst, src) asm volatile("cp.async.cg.shared.global [%0], [%1], 16;" :: "r"(dst), "l"(src) : "memory")
#define CPCOMMIT()     asm volatile("cp.async.commit_group;" ::: "memory")
#define CPWAIT1()      asm volatile("cp.async.wait_group 1;" ::: "memory")
#define CPWAIT0()      asm volatile("cp.async.wait_group 0;" ::: "memory")

// ---------- device scratch ----------
__device__ float g_proj[(size_t)M_PAD * NHID];                // 51.5 MB: proj = emb @ Wi
__device__ __nv_bfloat16 g_wt_hi[256 * EMBS];                 // Wi^T hi  [n][k]
__device__ __nv_bfloat16 g_wt_lo[256 * EMBS];                 // Wi^T lo  [n][k]

// =====================================================================
// Wi^T split-convert: fp32 -> (hi, lo) bf16, K zero-padded to 320.
// =====================================================================
__global__ __launch_bounds__(128) void convert_wi_kernel(const float* __restrict__ Wi)
{
    const int n = blockIdx.x, tid = threadIdx.x;
    for (int k = tid; k < EMBS; k += 128) {
        float v = (k < NEMB) ? Wi[k * NHID + n] : 0.f;
        __nv_bfloat16 h = __float2bfloat16(v);
        g_wt_hi[n * EMBS + k] = h;
        g_wt_lo[n * EMBS + k] = __float2bfloat16(v - __bfloat162float(h));
    }
}

// =====================================================================
// proj = emb @ Wi via 3-GEMM bf16 split on HMMA. CTA 128x128, 512 thr.
// (unchanged from R8)
// =====================================================================
#define RSTRIDE 144
#define AHI_OFF 0
#define ALO_OFF 18432
#define BHI_OFF 36864
#define BLO_OFF 55296
#define BUFSZ   73728
#define G8_SMEM (2 * BUFSZ + 64)

__global__ void __launch_bounds__(512, 1) proj_gemm(const float* __restrict__ emb)
{
    extern __shared__ __align__(16) char dsm[];
    const uint32_t smb = smem_u32(dsm);

    const int tid = threadIdx.x, wid = tid >> 5, lid = tid & 31;
    const int rbase = blockIdx.x * 128;
    const int cbase = blockIdx.y * 128;

    const int arow  = rbase + (tid >> 2);
    const int arowg = (arow < 50257) ? arow : 50256;
    const int aq    = (tid & 3) * 16;
    float4 af[4];

    auto lda = [&](int c) {
        #pragma unroll
        for (int i = 0; i < 4; i++) {
            int k = c * 64 + aq + i * 4;
            af[i] = (k < NEMB) ? *(const float4*)&emb[(size_t)arowg * NEMB + k]
                               : make_float4(0.f, 0.f, 0.f, 0.f);
        }
    };
    auto sta = [&](int buf) {
        uint32_t hw[8], lw[8];
        #pragma unroll
        for (int i = 0; i < 4; i++) {
            float4 f = af[i];
            __nv_bfloat16 hx = __float2bfloat16(f.x), hy = __float2bfloat16(f.y);
            __nv_bfloat16 hz = __float2bfloat16(f.z), hv = __float2bfloat16(f.w);
            hw[i * 2]     = bfpair(__bfloat162float(hx), __bfloat162float(hy));
            hw[i * 2 + 1] = bfpair(__bfloat162float(hz), __bfloat162float(hv));
            lw[i * 2]     = bfpair(f.x - __bfloat162float(hx), f.y - __bfloat162float(hy));
            lw[i * 2 + 1] = bfpair(f.z - __bfloat162float(hz), f.w - __bfloat162float(hv));
        }
        uint32_t doff = (uint32_t)((tid >> 2) * RSTRIDE + aq * 2);
        uint32_t base = smb + buf * BUFSZ;
        sts128(base + AHI_OFF + doff,      make_uint4(hw[0], hw[1], hw[2], hw[3]));
        sts128(base + AHI_OFF + doff + 16, make_uint4(hw[4], hw[5], hw[6], hw[7]));
        sts128(base + ALO_OFF + doff,      make_uint4(lw[0], lw[1], lw[2], lw[3]));
        sts128(base + ALO_OFF + doff + 16, make_uint4(lw[4], lw[5], lw[6], lw[7]));
    };
    auto issueB = [&](int c, int buf) {
        const uint32_t base = smb + buf * BUFSZ;
        #pragma unroll
        for (int q = 0; q < 2; q++) {
            int idx = tid + q * 512;
            int row = idx >> 3, seg = idx & 7;
            uint32_t doff = (uint32_t)(row * RSTRIDE + seg * 16);
            size_t boff = (size_t)(cbase + row) * EMBS + c * 64 + seg * 8;
            CP16(base + BHI_OFF + doff, (const char*)(g_wt_hi + boff));
            CP16(base + BLO_OFF + doff, (const char*)(g_wt_lo + boff));
        }
        CPCOMMIT();
    };

    const int wm = (wid >> 2) * 32;
    const int wn = (wid & 3) * 32;
    const uint32_t a_lane =
        (uint32_t)((wm + (lid & 7) + ((lid >> 3) & 1) * 8) * RSTRIDE + ((lid >> 4) & 1) * 16);
    const uint32_t b_lane =
        (uint32_t)((wn + (lid & 7) + ((lid >> 4) & 1) * 8) * RSTRIDE + ((lid >> 3) & 1) * 16);

    float acc[2][4][4];
    #pragma unroll
    for (int m = 0; m < 2; m++)
        #pragma unroll
        for (int j = 0; j < 4; j++)
            #pragma unroll
            for (int e = 0; e < 4; e++) acc[m][j][e] = 0.f;

    lda(0);
    issueB(0, 0);

    for (int c = 0; c < 5; c++) {
        const int buf = c & 1;
        sta(buf);
        if (c + 1 < 5) {
            lda(c + 1);
            issueB(c + 1, buf ^ 1);
            CPWAIT1();
        } else {
            CPWAIT0();
        }
        __syncthreads();

        const uint32_t bb = smb + buf * BUFSZ;
        #pragma unroll
        for (int ks = 0; ks < 4; ks++) {
            const uint32_t ko = ks * 32;
            uint32_t ah[2][4], al[2][4], bh[2][4], bl[2][4];
            #pragma unroll
            for (int mt = 0; mt < 2; mt++) {
                ldm4(ah[mt], bb + AHI_OFF + a_lane + mt * (16 * RSTRIDE) + ko);
                ldm4(al[mt], bb + ALO_OFF + a_lane + mt * (16 * RSTRIDE) + ko);
            }
            #pragma unroll
            for (int np = 0; np < 2; np++) {
                ldm4(bh[np], bb + BHI_OFF + b_lane + np * (16 * RSTRIDE) + ko);
                ldm4(bl[np], bb + BLO_OFF + b_lane + np * (16 * RSTRIDE) + ko);
            }
            #pragma unroll
            for (int mt = 0; mt < 2; mt++)
                #pragma unroll
                for (int j = 0; j < 4; j++)
                    mma16816(acc[mt][j], ah[mt], bh[j >> 1][(j & 1) * 2], bh[j >> 1][(j & 1) * 2 + 1]);
            #pragma unroll
            for (int mt = 0; mt < 2; mt++)
                #pragma unroll
                for (int j = 0; j < 4; j++)
                    mma16816(acc[mt][j], al[mt], bh[j >> 1][(j & 1) * 2], bh[j >> 1][(j & 1) * 2 + 1]);
            #pragma unroll
            for (int mt = 0; mt < 2; mt++)
                #pragma unroll
                for (int j = 0; j < 4; j++)
                    mma16816(acc[mt][j], ah[mt], bl[j >> 1][(j & 1) * 2], bl[j >> 1][(j & 1) * 2 + 1]);
        }
        __syncthreads();
    }

    const int g  = lid >> 2;
    const int i2 = (lid & 3) * 2;
    #pragma unroll
    for (int mt = 0; mt < 2; mt++) {
        #pragma unroll
        for (int j = 0; j < 4; j++) {
            int row = rbase + wm + mt * 16 + g;
            int col = cbase + wn + j * 8 + i2;
            *(float2*)&g_proj[(size_t)row * NHID + col] =
                make_float2(acc[mt][j][0], acc[mt][j][1]);
            *(float2*)&g_proj[(size_t)(row + 8) * NHID + col] =
                make_float2(acc[mt][j][2], acc[mt][j][3]);
        }
    }
}

// =====================================================================
// Phase 2: intra-warp K-split recurrence. 128 CTAs x 256 thr, 2 rows/CTA.
// Warp w owns cols [32w,32w+32). Lane: kh=lane>>4 k-half, cl=lane&15 ->
// cols {32w+cl, 32w+cl+16}, both rows, over its k-half.
// Partial exchange via shfl.xor(16) -> ONE barrier per step.
// h layout padded (row stride 268, half stride 132 floats) -> no bank dup.
// Wh: SQr=10 q-groups/half in smem (80 KB), RQr=22 in regs (176 regs).
// =====================================================================
#define SQr 10
#define RQr 22
#define WH_BYTES (2 * SQr * 256 * 16)          // 80 KB
#define HB_OFF   WH_BYTES
#define HROW     268                            // floats: row stride (pad)
#define HHALF    132                            // floats: k-half stride (pad)
#define HBUF     536                            // floats per h buffer (2 rows)
#define WSM_OFF  (HB_OFF + 2 * HBUF * 4)
#define P2_SMEM  (WSM_OFF + 2 * 512 * 4)

__device__ __forceinline__ int hidx(int buf, int row, int col) {
    return buf * HBUF + row * HROW + (col >> 7) * HHALF + (col & 127);
}

__global__ void __launch_bounds__(256, 1) rnn_kernel(
    const int* __restrict__ words,
    const float* __restrict__ Wh,
    const float* __restrict__ fcw,
    const float* __restrict__ fcb,
    float* __restrict__ out)
{
    extern __shared__ __align__(16) char smem[];
    ulonglong2* WhS = (ulonglong2*)smem;
    float*      hb  = (float*)(smem + HB_OFF);   // padded, double-buffered h
    int*        wsm = (int*)(smem + WSM_OFF);    // [2][512]

    const int tid = threadIdx.x;
    const int w   = tid >> 5, lane = tid & 31;
    const int kh  = lane >> 4;           // k-half this lane sums
    const int cl  = lane & 15;
    const int c0  = 32 * w + cl, c1 = c0 + 16;
    const int r0  = blockIdx.x * 2;

    // Wh smem: first SQr q-groups of each half, packed float4-over-k
    for (int i = tid; i < 2 * SQr * 256; i += 256) {
        int hf = i / (SQr * 256);
        int rem = i - hf * (SQr * 256);
        int q = rem >> 8, c = rem & 255;
        int kr = hf * 128 + 4 * q;
        float4 v = make_float4(Wh[kr * NHID + c],       Wh[(kr + 1) * NHID + c],
                               Wh[(kr + 2) * NHID + c], Wh[(kr + 3) * NHID + c]);
        ((float4*)smem)[i] = v;
    }
    for (int i = tid; i < SEQLEN; i += 256) {
        wsm[i]          = words[r0 * SEQLEN + i];
        wsm[SEQLEN + i] = words[(r0 + 1) * SEQLEN + i];
    }
    // Wh registers: remaining RQr q-groups of this k-half, cols c0 and c1
    ulonglong2 whr0[RQr], whr1[RQr];
    #pragma unroll
    for (int q = 0; q < RQr; q++) {
        int kr = kh * 128 + (SQr + q) * 4;
        whr0[q].x = pack2(Wh[kr * NHID + c0],       Wh[(kr + 1) * NHID + c0]);
        whr0[q].y = pack2(Wh[(kr + 2) * NHID + c0], Wh[(kr + 3) * NHID + c0]);
        whr1[q].x = pack2(Wh[kr * NHID + c1],       Wh[(kr + 1) * NHID + c1]);
        whr1[q].y = pack2(Wh[(kr + 2) * NHID + c1], Wh[(kr + 3) * NHID + c1]);
    }
    // h0 = 0 in buffer 0 (padded layout)
    hb[hidx(0, 0, tid)] = 0.f;
    hb[hidx(0, 1, tid)] = 0.f;
    __syncthreads();

    // x prefetch for the row this lane finalizes (row == kh), cols c0/c1
    float xa = g_proj[(size_t)wsm[kh * SEQLEN] * NHID + c0];
    float xb = g_proj[(size_t)wsm[kh * SEQLEN] * NHID + c1];

    int buf = 0;
    for (int t = 0; t < SEQLEN; t++) {
        // h groups for this lane's half: 16B-aligned padded layout
        const ulonglong2* H0 =
            (const ulonglong2*)(hb + buf * HBUF + kh * HHALF);
        const ulonglong2* H1 =
            (const ulonglong2*)(hb + buf * HBUF + HROW + kh * HHALF);

        ull a00 = 0, a01 = 0, a10 = 0, a11 = 0;   // [row][col]
        #pragma unroll
        for (int q = 0; q < SQr; q++) {
            ulonglong2 w0 = WhS[(kh * SQr + q) * 256 + c0];
            ulonglong2 w1 = WhS[(kh * SQr + q) * 256 + c1];
            ulonglong2 h0 = H0[q];
            ulonglong2 h1 = H1[q];
            fma2(a00, h0.x, w0.x); fma2(a00, h0.y, w0.y);
            fma2(a01, h0.x, w1.x); fma2(a01, h0.y, w1.y);
            fma2(a10, h1.x, w0.x); fma2(a10, h1.y, w0.y);
            fma2(a11, h1.x, w1.x); fma2(a11, h1.y, w1.y);
        }
        #pragma unroll
        for (int q = 0; q < RQr; q++) {
            ulonglong2 h0 = H0[SQr + q];
            ulonglong2 h1 = H1[SQr + q];
            fma2(a00, h0.x, whr0[q].x); fma2(a00, h0.y, whr0[q].y);
            fma2(a01, h0.x, whr1[q].x); fma2(a01, h0.y, whr1[q].y);
            fma2(a10, h1.x, whr0[q].x); fma2(a10, h1.y, whr0[q].y);
            fma2(a11, h1.x, whr1[q].x); fma2(a11, h1.y, whr1[q].y);
        }

        // prefetch next x early (LDG overlaps exchange + sigmoid)
        float nxa = 0.f, nxb = 0.f;
        if (t + 1 < SEQLEN) {
            size_t wrd = (size_t)wsm[kh * SEQLEN + t + 1] * NHID;
            nxa = g_proj[wrd + c0];
            nxb = g_proj[wrd + c1];
        }

        float2 s;
        s = unpack2(a00); float p00 = s.x + s.y;
        s = unpack2(a01); float p01 = s.x + s.y;
        s = unpack2(a10); float p10 = s.x + s.y;
        s = unpack2(a11); float p11 = s.x + s.y;

        // exchange with k-half partner (lane ^ 16) — no barrier
        float q00 = __shfl_xor_sync(0xffffffffu, p00, 16);
        float q01 = __shfl_xor_sync(0xffffffffu, p01, 16);
        float q10 = __shfl_xor_sync(0xffffffffu, p10, 16);
        float q11 = __shfl_xor_sync(0xffffffffu, p11, 16);

        // finalize row == kh for cols c0, c1
        float sa = kh ? (p10 + q10) : (p00 + q00);
        float sb = kh ? (p11 + q11) : (p01 + q01);
        float hna = sigmoidf(xa + sa);
        float hnb = sigmoidf(xb + sb);

        xa = nxa; xb = nxb;

        int nb = buf ^ 1;
        hb[hidx(nb, kh, c0)] = hna;
        hb[hidx(nb, kh, c1)] = hnb;
        __syncthreads();
        buf = nb;
    }

    // outputs
    out[256 + r0 * NHID + tid]       = hb[hidx(buf, 0, tid)];
    out[256 + (r0 + 1) * NHID + tid] = hb[hidx(buf, 1, tid)];

    int ww = tid >> 5, l = tid & 31;
    if (ww < 2) {
        float s = 0.f;
        #pragma unroll
        for (int q = 0; q < 8; q++)
            s += hb[hidx(buf, ww, l + q * 32)] * fcw[l + q * 32];
        #pragma unroll
        for (int o = 16; o; o >>= 1)
            s += __shfl_xor_sync(0xffffffffu, s, o);
        if (l == 0)
            out[r0 + ww] = sigmoidf(s + fcb[0]);
    }
}

// =====================================================================
extern "C" void kernel_launch(void* const* d_in, const int* in_sizes, int n_in,
                              void* d_out, int out_size)
{
    const int*   words = (const int*)  d_in[0];
    const float* emb   = (const float*)d_in[1];
    const float* Wi    = (const float*)d_in[2];
    const float* Wh    = (const float*)d_in[3];
    const float* fcw   = (const float*)d_in[4];
    const float* fcb   = (const float*)d_in[5];
    float*       out   = (float*)d_out;

    cudaFuncSetAttribute(proj_gemm, cudaFuncAttributeMaxDynamicSharedMemorySize, G8_SMEM);
    cudaFuncSetAttribute(rnn_kernel, cudaFuncAttributeMaxDynamicSharedMemorySize, P2_SMEM);

    convert_wi_kernel<<<NHID, 128>>>(Wi);
    proj_gemm<<<dim3(M_PAD / 128, NHID / 128), 512, G8_SMEM>>>(emb);
    rnn_kernel<<<BATCHN / 2, 256, P2_SMEM>>>(words, Wh, fcw, fcb, out);
}

// round 12
// speedup vs baseline: 2.6511x; 1.0409x over previous
#include <cuda_runtime.h>
#include <cuda_bf16.h>
#include <cstdint>

#define BATCHN 256
#define SEQLEN 512
#define NEMB   300
#define NHID   256
#define EMBS   320          // padded K (5 chunks of 64)
#define M_PAD  50304        // vocab rows padded to 128

typedef unsigned long long ull;

// ---------- packed f32x2 helpers (rnn path) ----------
__device__ __forceinline__ void fma2(ull &d, ull a, ull b) {
    asm("fma.rn.f32x2 %0, %1, %2, %0;" : "+l"(d) : "l"(a), "l"(b));
}
__device__ __forceinline__ ull pack2(float x, float y) {
    ull r; asm("mov.b64 %0, {%1, %2};" : "=l"(r) : "f"(x), "f"(y)); return r;
}
__device__ __forceinline__ float2 unpack2(ull v) {
    float2 r; asm("mov.b64 {%0, %1}, %2;" : "=f"(r.x), "=f"(r.y) : "l"(v)); return r;
}
__device__ __forceinline__ float sigmoidf(float z) {
    return 1.0f / (1.0f + __expf(-z));
}

// ---------- HMMA / ldmatrix / cp.async helpers ----------
__device__ __forceinline__ uint32_t smem_u32(const void* p) {
    uint32_t a;
    asm("{ .reg .u64 t; cvta.to.shared.u64 t, %1; cvt.u32.u64 %0, t; }" : "=r"(a) : "l"(p));
    return a;
}
__device__ __forceinline__ void ldm4(uint32_t* r, uint32_t addr) {
    asm volatile("ldmatrix.sync.aligned.m8n8.x4.shared.b16 {%0,%1,%2,%3}, [%4];"
                 : "=r"(r[0]), "=r"(r[1]), "=r"(r[2]), "=r"(r[3]) : "r"(addr));
}
__device__ __forceinline__ void mma16816(float* d, const uint32_t* a, uint32_t b0, uint32_t b1) {
    asm volatile(
        "mma.sync.aligned.m16n8k16.row.col.f32.bf16.bf16.f32 "
        "{%0,%1,%2,%3}, {%4,%5,%6,%7}, {%8,%9}, {%0,%1,%2,%3};"
        : "+f"(d[0]), "+f"(d[1]), "+f"(d[2]), "+f"(d[3])
        : "r"(a[0]), "r"(a[1]), "r"(a[2]), "r"(a[3]), "r"(b0), "r"(b1));
}
__device__ __forceinline__ uint32_t bfpair(float a, float b) {
    __nv_bfloat162 t = __floats2bfloat162_rn(a, b);
    return *(uint32_t*)&t;
}
__device__ __forceinline__ void sts128(uint32_t addr, uint4 v) {
    asm volatile("st.shared.v4.b32 [%0], {%1,%2,%3,%4};"
                 :: "r"(addr), "r"(v.x), "r"(v.y), "r"(v.z), "r"(v.w) : "memory");
}
#define CP16(dst, src) asm volatile("cp.async.cg.shared.global [%0], [%1], 16;" :: "r"(dst), "l"(src) : "memory")
#define CPCOMMIT()     asm volatile("cp.async.commit_group;" ::: "memory")
#define CPWAIT1()      asm volatile("cp.async.wait_group 1;" ::: "memory")
#define CPWAIT0()      asm volatile("cp.async.wait_group 0;" ::: "memory")

// ---------- device scratch ----------
__device__ float g_proj[(size_t)M_PAD * NHID];                // 51.5 MB: proj = emb @ Wi
__device__ __nv_bfloat16 g_wt_hi[256 * EMBS];                 // Wi^T hi  [n][k]
__device__ __nv_bfloat16 g_wt_lo[256 * EMBS];                 // Wi^T lo  [n][k]

// =====================================================================
// Wi^T split-convert: fp32 -> (hi, lo) bf16, K zero-padded to 320.
// =====================================================================
__global__ __launch_bounds__(128) void convert_wi_kernel(const float* __restrict__ Wi)
{
    const int n = blockIdx.x, tid = threadIdx.x;
    for (int k = tid; k < EMBS; k += 128) {
        float v = (k < NEMB) ? Wi[k * NHID + n] : 0.f;
        __nv_bfloat16 h = __float2bfloat16(v);
        g_wt_hi[n * EMBS + k] = h;
        g_wt_lo[n * EMBS + k] = __float2bfloat16(v - __bfloat162float(h));
    }
}

// =====================================================================
// proj = emb @ Wi via 3-GEMM bf16 split on HMMA. CTA 128x128, 512 thr.
// (unchanged from R8)
// =====================================================================
#define RSTRIDE 144
#define AHI_OFF 0
#define ALO_OFF 18432
#define BHI_OFF 36864
#define BLO_OFF 55296
#define BUFSZ   73728
#define G8_SMEM (2 * BUFSZ + 64)

__global__ void __launch_bounds__(512, 1) proj_gemm(const float* __restrict__ emb)
{
    extern __shared__ __align__(16) char dsm[];
    const uint32_t smb = smem_u32(dsm);

    const int tid = threadIdx.x, wid = tid >> 5, lid = tid & 31;
    const int rbase = blockIdx.x * 128;
    const int cbase = blockIdx.y * 128;

    const int arow  = rbase + (tid >> 2);
    const int arowg = (arow < 50257) ? arow : 50256;
    const int aq    = (tid & 3) * 16;
    float4 af[4];

    auto lda = [&](int c) {
        #pragma unroll
        for (int i = 0; i < 4; i++) {
            int k = c * 64 + aq + i * 4;
            af[i] = (k < NEMB) ? *(const float4*)&emb[(size_t)arowg * NEMB + k]
                               : make_float4(0.f, 0.f, 0.f, 0.f);
        }
    };
    auto sta = [&](int buf) {
        uint32_t hw[8], lw[8];
        #pragma unroll
        for (int i = 0; i < 4; i++) {
            float4 f = af[i];
            __nv_bfloat16 hx = __float2bfloat16(f.x), hy = __float2bfloat16(f.y);
            __nv_bfloat16 hz = __float2bfloat16(f.z), hv = __float2bfloat16(f.w);
            hw[i * 2]     = bfpair(__bfloat162float(hx), __bfloat162float(hy));
            hw[i * 2 + 1] = bfpair(__bfloat162float(hz), __bfloat162float(hv));
            lw[i * 2]     = bfpair(f.x - __bfloat162float(hx), f.y - __bfloat162float(hy));
            lw[i * 2 + 1] = bfpair(f.z - __bfloat162float(hz), f.w - __bfloat162float(hv));
        }
        uint32_t doff = (uint32_t)((tid >> 2) * RSTRIDE + aq * 2);
        uint32_t base = smb + buf * BUFSZ;
        sts128(base + AHI_OFF + doff,      make_uint4(hw[0], hw[1], hw[2], hw[3]));
        sts128(base + AHI_OFF + doff + 16, make_uint4(hw[4], hw[5], hw[6], hw[7]));
        sts128(base + ALO_OFF + doff,      make_uint4(lw[0], lw[1], lw[2], lw[3]));
        sts128(base + ALO_OFF + doff + 16, make_uint4(lw[4], lw[5], lw[6], lw[7]));
    };
    auto issueB = [&](int c, int buf) {
        const uint32_t base = smb + buf * BUFSZ;
        #pragma unroll
        for (int q = 0; q < 2; q++) {
            int idx = tid + q * 512;
            int row = idx >> 3, seg = idx & 7;
            uint32_t doff = (uint32_t)(row * RSTRIDE + seg * 16);
            size_t boff = (size_t)(cbase + row) * EMBS + c * 64 + seg * 8;
            CP16(base + BHI_OFF + doff, (const char*)(g_wt_hi + boff));
            CP16(base + BLO_OFF + doff, (const char*)(g_wt_lo + boff));
        }
        CPCOMMIT();
    };

    const int wm = (wid >> 2) * 32;
    const int wn = (wid & 3) * 32;
    const uint32_t a_lane =
        (uint32_t)((wm + (lid & 7) + ((lid >> 3) & 1) * 8) * RSTRIDE + ((lid >> 4) & 1) * 16);
    const uint32_t b_lane =
        (uint32_t)((wn + (lid & 7) + ((lid >> 4) & 1) * 8) * RSTRIDE + ((lid >> 3) & 1) * 16);

    float acc[2][4][4];
    #pragma unroll
    for (int m = 0; m < 2; m++)
        #pragma unroll
        for (int j = 0; j < 4; j++)
            #pragma unroll
            for (int e = 0; e < 4; e++) acc[m][j][e] = 0.f;

    lda(0);
    issueB(0, 0);

    for (int c = 0; c < 5; c++) {
        const int buf = c & 1;
        sta(buf);
        if (c + 1 < 5) {
            lda(c + 1);
            issueB(c + 1, buf ^ 1);
            CPWAIT1();
        } else {
            CPWAIT0();
        }
        __syncthreads();

        const uint32_t bb = smb + buf * BUFSZ;
        #pragma unroll
        for (int ks = 0; ks < 4; ks++) {
            const uint32_t ko = ks * 32;
            uint32_t ah[2][4], al[2][4], bh[2][4], bl[2][4];
            #pragma unroll
            for (int mt = 0; mt < 2; mt++) {
                ldm4(ah[mt], bb + AHI_OFF + a_lane + mt * (16 * RSTRIDE) + ko);
                ldm4(al[mt], bb + ALO_OFF + a_lane + mt * (16 * RSTRIDE) + ko);
            }
            #pragma unroll
            for (int np = 0; np < 2; np++) {
                ldm4(bh[np], bb + BHI_OFF + b_lane + np * (16 * RSTRIDE) + ko);
                ldm4(bl[np], bb + BLO_OFF + b_lane + np * (16 * RSTRIDE) + ko);
            }
            #pragma unroll
            for (int mt = 0; mt < 2; mt++)
                #pragma unroll
                for (int j = 0; j < 4; j++)
                    mma16816(acc[mt][j], ah[mt], bh[j >> 1][(j & 1) * 2], bh[j >> 1][(j & 1) * 2 + 1]);
            #pragma unroll
            for (int mt = 0; mt < 2; mt++)
                #pragma unroll
                for (int j = 0; j < 4; j++)
                    mma16816(acc[mt][j], al[mt], bh[j >> 1][(j & 1) * 2], bh[j >> 1][(j & 1) * 2 + 1]);
            #pragma unroll
            for (int mt = 0; mt < 2; mt++)
                #pragma unroll
                for (int j = 0; j < 4; j++)
                    mma16816(acc[mt][j], ah[mt], bl[j >> 1][(j & 1) * 2], bl[j >> 1][(j & 1) * 2 + 1]);
        }
        __syncthreads();
    }

    const int g  = lid >> 2;
    const int i2 = (lid & 3) * 2;
    #pragma unroll
    for (int mt = 0; mt < 2; mt++) {
        #pragma unroll
        for (int j = 0; j < 4; j++) {
            int row = rbase + wm + mt * 16 + g;
            int col = cbase + wn + j * 8 + i2;
            *(float2*)&g_proj[(size_t)row * NHID + col] =
                make_float2(acc[mt][j][0], acc[mt][j][1]);
            *(float2*)&g_proj[(size_t)(row + 8) * NHID + col] =
                make_float2(acc[mt][j][2], acc[mt][j][3]);
        }
    }
}

// =====================================================================
// Phase 2: 4-way intra-warp K-split recurrence. 128 CTAs x 256 thr.
// Lane: kh=lane>>3 (k-quarter, 64 elems), cl=lane&7 -> 4 cols
// {32w+cl, +8, +16, +24}, both rows.
// Exchange: butterfly shfl.xor(8), shfl.xor(16); lane kh finalizes
// (row = kh&1, col-group = kh>>1) -> 2 outputs/lane. ONE barrier/step.
// h layout: quarter stride 68 floats (banks 0-3/4-7/8-11/12-15), row 272.
// Wh: 5 q-groups/quarter in smem (80 KB), 11 in regs (4 cols x 11 = 176).
// Crossbar demand ~920 wf/step (was 1160); fma 1024 cyc/SMSP now binds.
// =====================================================================
#define SQ4 5
#define RQ4 11
#define WH4_BYTES (4 * SQ4 * 256 * 16)          // 80 KB
#define HB_OFF   WH4_BYTES
#define HQ       68                              // floats: k-quarter stride
#define HROW     272                             // floats: row stride
#define HBUF     544                             // floats per h buffer
#define WSM_OFF  (HB_OFF + 2 * HBUF * 4)
#define P2_SMEM  (WSM_OFF + 2 * 512 * 4)

__device__ __forceinline__ int hidx(int buf, int row, int col) {
    return buf * HBUF + row * HROW + (col >> 6) * HQ + (col & 63);
}

__global__ void __launch_bounds__(256, 1) rnn_kernel(
    const int* __restrict__ words,
    const float* __restrict__ Wh,
    const float* __restrict__ fcw,
    const float* __restrict__ fcb,
    float* __restrict__ out)
{
    extern __shared__ __align__(16) char smem[];
    ulonglong2* WhS = (ulonglong2*)smem;         // [4][SQ4][256]
    float*      hb  = (float*)(smem + HB_OFF);   // padded, double-buffered h
    int*        wsm = (int*)(smem + WSM_OFF);    // [2][512]

    const int tid  = threadIdx.x;
    const int w    = tid >> 5, lane = tid & 31;
    const int kh   = lane >> 3;          // k-quarter this lane sums
    const int cl   = lane & 7;
    const int cb   = 32 * w + cl;        // col base; cols cb + 8*ci
    const int r0   = blockIdx.x * 2;

    // Wh smem: first SQ4 q-groups of each quarter, packed float4-over-k
    for (int i = tid; i < 4 * SQ4 * 256; i += 256) {
        int qt  = i / (SQ4 * 256);
        int rem = i - qt * (SQ4 * 256);
        int q = rem >> 8, c = rem & 255;
        int kr = qt * 64 + 4 * q;
        float4 v = make_float4(Wh[kr * NHID + c],       Wh[(kr + 1) * NHID + c],
                               Wh[(kr + 2) * NHID + c], Wh[(kr + 3) * NHID + c]);
        ((float4*)smem)[i] = v;
    }
    for (int i = tid; i < SEQLEN; i += 256) {
        wsm[i]          = words[r0 * SEQLEN + i];
        wsm[SEQLEN + i] = words[(r0 + 1) * SEQLEN + i];
    }
    // Wh registers: remaining RQ4 q-groups of this quarter, 4 cols
    ulonglong2 whr[4][RQ4];
    #pragma unroll
    for (int ci = 0; ci < 4; ci++) {
        int c = cb + 8 * ci;
        #pragma unroll
        for (int q = 0; q < RQ4; q++) {
            int kr = kh * 64 + (SQ4 + q) * 4;
            whr[ci][q].x = pack2(Wh[kr * NHID + c],       Wh[(kr + 1) * NHID + c]);
            whr[ci][q].y = pack2(Wh[(kr + 2) * NHID + c], Wh[(kr + 3) * NHID + c]);
        }
    }
    hb[hidx(0, 0, tid)] = 0.f;
    hb[hidx(0, 1, tid)] = 0.f;
    __syncthreads();

    // finalize assignment: row = kh&1, col-group = kh>>1 -> cols cA, cB
    const int frow = kh & 1;
    const int cA   = cb + 16 * (kh >> 1);
    const int cB   = cA + 8;

    float xa = g_proj[(size_t)wsm[frow * SEQLEN] * NHID + cA];
    float xb = g_proj[(size_t)wsm[frow * SEQLEN] * NHID + cB];

    int buf = 0;
    for (int t = 0; t < SEQLEN; t++) {
        const ulonglong2* H0 =
            (const ulonglong2*)(hb + buf * HBUF + kh * HQ);
        const ulonglong2* H1 =
            (const ulonglong2*)(hb + buf * HBUF + HROW + kh * HQ);

        ull a0[4] = {0, 0, 0, 0};     // row 0, cols ci
        ull a1[4] = {0, 0, 0, 0};     // row 1
        #pragma unroll
        for (int q = 0; q < SQ4; q++) {
            ulonglong2 h0 = H0[q];
            ulonglong2 h1 = H1[q];
            #pragma unroll
            for (int ci = 0; ci < 4; ci++) {
                ulonglong2 wv = WhS[(kh * SQ4 + q) * 256 + cb + 8 * ci];
                fma2(a0[ci], h0.x, wv.x); fma2(a0[ci], h0.y, wv.y);
                fma2(a1[ci], h1.x, wv.x); fma2(a1[ci], h1.y, wv.y);
            }
        }
        #pragma unroll
        for (int q = 0; q < RQ4; q++) {
            ulonglong2 h0 = H0[SQ4 + q];
            ulonglong2 h1 = H1[SQ4 + q];
            #pragma unroll
            for (int ci = 0; ci < 4; ci++) {
                fma2(a0[ci], h0.x, whr[ci][q].x); fma2(a0[ci], h0.y, whr[ci][q].y);
                fma2(a1[ci], h1.x, whr[ci][q].x); fma2(a1[ci], h1.y, whr[ci][q].y);
            }
        }

        // prefetch next x early (overlaps exchange + sigmoid)
        float nxa = 0.f, nxb = 0.f;
        if (t + 1 < SEQLEN) {
            size_t wrd = (size_t)wsm[frow * SEQLEN + t + 1] * NHID;
            nxa = g_proj[wrd + cA];
            nxb = g_proj[wrd + cB];
        }

        float p[8];
        #pragma unroll
        for (int ci = 0; ci < 4; ci++) {
            float2 s0 = unpack2(a0[ci]);
            float2 s1 = unpack2(a1[ci]);
            p[ci]     = s0.x + s0.y;
            p[4 + ci] = s1.x + s1.y;
        }
        // butterfly over the 4 k-quarters (lanes cl, cl+8, cl+16, cl+24)
        #pragma unroll
        for (int i = 0; i < 8; i++)
            p[i] += __shfl_xor_sync(0xffffffffu, p[i], 8);
        #pragma unroll
        for (int i = 0; i < 8; i++)
            p[i] += __shfl_xor_sync(0xffffffffu, p[i], 16);

        // finalize: row frow, cols cA (ci = 2*(kh>>1)) and cB (ci+1)
        const int cib = (kh >> 1) * 2;
        float sa = p[frow * 4 + cib];
        float sb = p[frow * 4 + cib + 1];
        float hna = sigmoidf(xa + sa);
        float hnb = sigmoidf(xb + sb);

        xa = nxa; xb = nxb;

        int nb = buf ^ 1;
        hb[hidx(nb, frow, cA)] = hna;
        hb[hidx(nb, frow, cB)] = hnb;
        __syncthreads();
        buf = nb;
    }

    // outputs
    out[256 + r0 * NHID + tid]       = hb[hidx(buf, 0, tid)];
    out[256 + (r0 + 1) * NHID + tid] = hb[hidx(buf, 1, tid)];

    int ww = tid >> 5, l = tid & 31;
    if (ww < 2) {
        float s = 0.f;
        #pragma unroll
        for (int q = 0; q < 8; q++)
            s += hb[hidx(buf, ww, l + q * 32)] * fcw[l + q * 32];
        #pragma unroll
        for (int o = 16; o; o >>= 1)
            s += __shfl_xor_sync(0xffffffffu, s, o);
        if (l == 0)
            out[r0 + ww] = sigmoidf(s + fcb[0]);
    }
}

// =====================================================================
extern "C" void kernel_launch(void* const* d_in, const int* in_sizes, int n_in,
                              void* d_out, int out_size)
{
    const int*   words = (const int*)  d_in[0];
    const float* emb   = (const float*)d_in[1];
    const float* Wi    = (const float*)d_in[2];
    const float* Wh    = (const float*)d_in[3];
    const float* fcw   = (const float*)d_in[4];
    const float* fcb   = (const float*)d_in[5];
    float*       out   = (float*)d_out;

    cudaFuncSetAttribute(proj_gemm, cudaFuncAttributeMaxDynamicSharedMemorySize, G8_SMEM);
    cudaFuncSetAttribute(rnn_kernel, cudaFuncAttributeMaxDynamicSharedMemorySize, P2_SMEM);

    convert_wi_kernel<<<NHID, 128>>>(Wi);
    proj_gemm<<<dim3(M_PAD / 128, NHID / 128), 512, G8_SMEM>>>(emb);
    rnn_kernel<<<BATCHN / 2, 256, P2_SMEM>>>(words, Wh, fcw, fcb, out);
}